// round 2
// baseline (speedup 1.0000x reference)
#include <cuda_runtime.h>

// Problem constants
#define BN_   10000
#define T_    8
#define C_    64
#define NM_   3
#define E_    160000
#define NTOT_ (T_ * BN_)        // 80000 node-rows
#define HTOT_ (NTOT_ * C_)      // 5,120,000

// Scratch (device globals: allocation-free rule)
__device__ __align__(16) float g_hnew[HTOT_];   // h after time conv (T,BN,C) flat
__device__ __align__(16) float g_A[HTOT_];      // h_new @ We1[0:64]  + b_e1
__device__ __align__(16) float g_B[HTOT_];      // h_new @ We1[64:128]
__device__ __align__(16) float g_agg[HTOT_];    // segment sums
__device__ __align__(16) float g_d2[E_];        // squared distances per base edge

// 8-point DFT twiddles
__constant__ float CT8[8] = {1.f,  0.70710678118654752f, 0.f, -0.70710678118654752f,
                             -1.f, -0.70710678118654752f, 0.f,  0.70710678118654752f};
__constant__ float ST8[8] = {0.f,  0.70710678118654752f, 1.f,  0.70710678118654752f,
                             0.f, -0.70710678118654752f, -1.f, -0.70710678118654752f};

typedef unsigned long long ull;

__device__ __forceinline__ float silu_f(float x)    { return x / (1.f + __expf(-x)); }
__device__ __forceinline__ float sigmoid_f(float x) { return 1.f / (1.f + __expf(-x)); }

__device__ __forceinline__ ull pk2(float lo, float hi) {
    ull r; asm("mov.b64 %0,{%1,%2};" : "=l"(r) : "f"(lo), "f"(hi)); return r;
}
__device__ __forceinline__ void upk2(ull v, float& lo, float& hi) {
    asm("mov.b64 {%0,%1},%2;" : "=f"(lo), "=f"(hi) : "l"(v));
}
__device__ __forceinline__ ull f2fma(ull a, ull b, ull c) {
    ull d; asm("fma.rn.f32x2 %0,%1,%2,%3;" : "=l"(d) : "l"(a), "l"(b), "l"(c)); return d;
}

// ---------------------------------------------------------------------------
// Kernel 1: TimeConv on h.  h_new = h + leaky_relu(spectral_conv(h), 0.2)
// ---------------------------------------------------------------------------
__global__ void k_time_h(const float* __restrict__ h,
                         const float* __restrict__ whr,
                         const float* __restrict__ whi) {
    extern __shared__ float sm[];
    float* swr = sm;            // [3][64][64]
    float* swi = sm + 12288;
    float* sxf = sm + 24576;    // [4 grp][64 i][6]
    const int tid = threadIdx.x;

    for (int idx = tid; idx < C_ * C_ * NM_; idx += blockDim.x) {
        int i   = idx / (C_ * NM_);
        int rem = idx - i * (C_ * NM_);
        int o   = rem / NM_;
        int k   = rem - o * NM_;
        int d   = k * (C_ * C_) + i * C_ + o;
        swr[d] = whr[idx];
        swi[d] = whi[idx];
    }
    __syncthreads();

    const int grp = tid >> 6;
    const int l   = tid & 63;

    for (int nb = blockIdx.x * 4; nb < BN_; nb += gridDim.x * 4) {
        int node = nb + grp;
        if (node < BN_) {
            float xv[8];
#pragma unroll
            for (int t = 0; t < 8; ++t) xv[t] = h[t * (BN_ * C_) + node * C_ + l];
            float xr0 = 0.f, xr1 = 0.f, xi1 = 0.f, xr2 = 0.f, xi2 = 0.f;
#pragma unroll
            for (int t = 0; t < 8; ++t) {
                xr0 += xv[t];
                xr1 += xv[t] * CT8[t];
                xi1 -= xv[t] * ST8[t];
                xr2 += xv[t] * CT8[(2 * t) & 7];
                xi2 -= xv[t] * ST8[(2 * t) & 7];
            }
            float* p = sxf + grp * 384 + l * 6;
            p[0] = xr0; p[1] = 0.f; p[2] = xr1; p[3] = xi1; p[4] = xr2; p[5] = xi2;
        }
        __syncthreads();
        if (node < BN_) {
            float omr[3] = {0.f, 0.f, 0.f};
            float omi[3] = {0.f, 0.f, 0.f};
            const float* xb = sxf + grp * 384;
            for (int i = 0; i < C_; ++i) {
#pragma unroll
                for (int k = 0; k < 3; ++k) {
                    float xr = xb[i * 6 + 2 * k];
                    float xi = xb[i * 6 + 2 * k + 1];
                    float wr = swr[k * 4096 + i * 64 + l];
                    float wi = swi[k * 4096 + i * 64 + l];
                    omr[k] += xr * wr - xi * wi;
                    omi[k] += xr * wi + xi * wr;
                }
            }
#pragma unroll
            for (int t = 0; t < 8; ++t) {
                float val = omr[0]
                    + 2.f * (omr[1] * CT8[t]           - omi[1] * ST8[t])
                    + 2.f * (omr[2] * CT8[(2 * t) & 7] - omi[2] * ST8[(2 * t) & 7]);
                val *= 0.125f;
                float lr = val > 0.f ? val : 0.2f * val;
                int off = t * (BN_ * C_) + node * C_ + l;
                g_hnew[off] = h[off] + lr;
            }
        }
        __syncthreads();
    }
}

// ---------------------------------------------------------------------------
// Kernel 2: TimeConvX on velocity
// ---------------------------------------------------------------------------
__global__ void k_time_v(const float* __restrict__ vel,
                         const float* __restrict__ wvr,
                         const float* __restrict__ wvi,
                         float* __restrict__ out) {
    int j = blockIdx.x * blockDim.x + threadIdx.x;
    if (j >= BN_ * 3) return;
    int b = j / 3, d = j - b * 3;
    float xv[8];
#pragma unroll
    for (int t = 0; t < 8; ++t) xv[t] = vel[b * (T_ * 3) + t * 3 + d];
    float xr0 = 0.f, xr1 = 0.f, xi1 = 0.f, xr2 = 0.f, xi2 = 0.f;
#pragma unroll
    for (int t = 0; t < 8; ++t) {
        xr0 += xv[t];
        xr1 += xv[t] * CT8[t];
        xi1 -= xv[t] * ST8[t];
        xr2 += xv[t] * CT8[(2 * t) & 7];
        xi2 -= xv[t] * ST8[(2 * t) & 7];
    }
    float w0r = wvr[0];
    float w1r = wvr[1], w1i = wvi[1];
    float w2r = wvr[2], w2i = wvi[2];
    float yr0 = xr0 * w0r;
    float yr1 = xr1 * w1r - xi1 * w1i;
    float yi1 = xr1 * w1i + xi1 * w1r;
    float yr2 = xr2 * w2r - xi2 * w2i;
    float yi2 = xr2 * w2i + xi2 * w2r;
#pragma unroll
    for (int t = 0; t < 8; ++t) {
        float val = 0.125f * (yr0
            + 2.f * (yr1 * CT8[t]           - yi1 * ST8[t])
            + 2.f * (yr2 * CT8[(2 * t) & 7] - yi2 * ST8[(2 * t) & 7]));
        out[b * (T_ * 3) + t * 3 + d] = xv[t] + val;
    }
}

// ---------------------------------------------------------------------------
// Kernel 3: per-base-edge squared distance
// ---------------------------------------------------------------------------
__global__ void k_d2(const float* __restrict__ x, const int* __restrict__ ei) {
    int e = blockIdx.x * blockDim.x + threadIdx.x;
    if (e >= E_) return;
    int r = ei[e];
    int c = ei[E_ + e];
    float dx = x[r * 3 + 0] - x[c * 3 + 0];
    float dy = x[r * 3 + 1] - x[c * 3 + 1];
    float dz = x[r * 3 + 2] - x[c * 3 + 2];
    g_d2[e] = dx * dx + dy * dy + dz * dz;
}

// ---------------------------------------------------------------------------
// Kernel 4: A/B precompute, 4 lanes per node, 64 nodes per 256-thread block.
// A = h@We1[0:64] + b_e1, B = h@We1[64:128]. Also zeroes agg.
// ---------------------------------------------------------------------------
__global__ void __launch_bounds__(256) k_ab(const float* __restrict__ We1,
                                            const float* __restrict__ be1) {
    extern __shared__ float sm[];
    float* sW = sm;                 // 128*64 = 8192
    float* sh = sm + 8192;          // 64*68 = 4352
    float* sb = sm + 8192 + 4352;   // 64
    const int tid = threadIdx.x;
    for (int i = tid; i < 8192; i += 256) sW[i] = We1[i];
    if (tid < 64) sb[tid] = be1[tid];

    const int q = tid & 3, s = tid >> 2;
    const int n = blockIdx.x * 64 + s;

    // phase 1: stage h row chunk into smem, zero agg chunk
    {
        const float4* hp = (const float4*)(g_hnew + n * 64 + q * 16);
        float4* shp = (float4*)(sh + s * 68 + q * 16);
        float4* agp = (float4*)(g_agg + n * 64 + q * 16);
        float4 z = make_float4(0.f, 0.f, 0.f, 0.f);
#pragma unroll
        for (int jj = 0; jj < 4; ++jj) { shp[jj] = hp[jj]; agp[jj] = z; }
    }
    __syncthreads();

    ull accA[8], accB[8];
#pragma unroll
    for (int jj = 0; jj < 8; ++jj) {
        accA[jj] = pk2(sb[q * 16 + 2 * jj], sb[q * 16 + 2 * jj + 1]);
        accB[jj] = pk2(0.f, 0.f);
    }
    const float* hr = sh + s * 68;
#pragma unroll 4
    for (int k = 0; k < 64; ++k) {
        float mv = hr[k];
        ull mk = pk2(mv, mv);
        const float4* wa = (const float4*)(sW + k * 64 + q * 16);
        const float4* wb = (const float4*)(sW + (64 + k) * 64 + q * 16);
#pragma unroll
        for (int jj = 0; jj < 4; ++jj) {
            float4 a = wa[jj];
            float4 b = wb[jj];
            accA[2*jj]   = f2fma(mk, pk2(a.x, a.y), accA[2*jj]);
            accA[2*jj+1] = f2fma(mk, pk2(a.z, a.w), accA[2*jj+1]);
            accB[2*jj]   = f2fma(mk, pk2(b.x, b.y), accB[2*jj]);
            accB[2*jj+1] = f2fma(mk, pk2(b.z, b.w), accB[2*jj+1]);
        }
    }
    float4* ap = (float4*)(g_A + n * 64 + q * 16);
    float4* bp = (float4*)(g_B + n * 64 + q * 16);
#pragma unroll
    for (int jj = 0; jj < 4; ++jj) {
        float4 va, vb;
        upk2(accA[2*jj],   va.x, va.y); upk2(accA[2*jj+1], va.z, va.w);
        upk2(accB[2*jj],   vb.x, vb.y); upk2(accB[2*jj+1], vb.z, vb.w);
        ap[jj] = va; bp[jj] = vb;
    }
}

// ---------------------------------------------------------------------------
// Kernel 5: edge messages. 4 lanes/edge, 2 edges/thread, 128 edges/block.
// ---------------------------------------------------------------------------
__global__ void __launch_bounds__(256) k_edge(const int* __restrict__ ei,
                                              const float* __restrict__ We1,
                                              const float* __restrict__ We2,
                                              const float* __restrict__ be2,
                                              const float* __restrict__ Wg,
                                              const float* __restrict__ bg) {
    extern __shared__ float sm[];
    float* sW2 = sm;                   // 4096
    float* sm1 = sm + 4096;            // 128*68 = 8704
    float* swl = sm + 4096 + 8704;     // 64
    float* sg  = swl + 64;             // 64
    float* sb2 = sg + 64;              // 64
    const int tid = threadIdx.x;
    for (int i = tid; i < 4096; i += 256) sW2[i] = We2[i];
    if (tid < 64) {
        swl[tid] = We1[128 * 64 + tid];
        sg[tid]  = Wg[tid];
        sb2[tid] = be2[tid];
    }
    __syncthreads();

    const int q = tid & 3, s = tid >> 2;
    const int t  = blockIdx.x / 1250;                 // 1250 blocks per time slice
    const int jb = (blockIdx.x - t * 1250) * 128;

    int rbs[2];
    // phase 1: m1 = silu(A[rb] + B[cb] + d2*wl) -> smem
#pragma unroll
    for (int p = 0; p < 2; ++p) {
        int e = s + p * 64;
        int j = jb + e;
        int r = __ldg(ei + j);
        int c = __ldg(ei + E_ + j);
        rbs[p] = t * BN_ + r;
        int cb = t * BN_ + c;
        float dd = g_d2[j];
        const float4* Ap = (const float4*)(g_A + rbs[p] * 64 + q * 16);
        const float4* Bp = (const float4*)(g_B + cb * 64 + q * 16);
        const float4* wl = (const float4*)(swl + q * 16);
        float4* dst = (float4*)(sm1 + e * 68 + q * 16);
#pragma unroll
        for (int jj = 0; jj < 4; ++jj) {
            float4 a = Ap[jj], b = Bp[jj], w = wl[jj];
            float4 o;
            o.x = silu_f(a.x + b.x + dd * w.x);
            o.y = silu_f(a.y + b.y + dd * w.y);
            o.z = silu_f(a.z + b.z + dd * w.z);
            o.w = silu_f(a.w + b.w + dd * w.w);
            dst[jj] = o;
        }
    }
    __syncthreads();

    // phase 2: m2 = m1 @ We2 + b_e2 (packed f32x2, two edges per thread)
    ull acc0[8], acc1[8];
#pragma unroll
    for (int jj = 0; jj < 8; ++jj) {
        ull b = pk2(sb2[q * 16 + 2 * jj], sb2[q * 16 + 2 * jj + 1]);
        acc0[jj] = b; acc1[jj] = b;
    }
    const float* m0r = sm1 + s * 68;
    const float* m1r = sm1 + (s + 64) * 68;
#pragma unroll 4
    for (int k = 0; k < 64; ++k) {
        float v0 = m0r[k], v1 = m1r[k];
        ull mk0 = pk2(v0, v0);
        ull mk1 = pk2(v1, v1);
        const float4* wr = (const float4*)(sW2 + k * 64 + q * 16);
#pragma unroll
        for (int jj = 0; jj < 4; ++jj) {
            float4 w = wr[jj];
            ull wlo = pk2(w.x, w.y);
            ull whi = pk2(w.z, w.w);
            acc0[2*jj]   = f2fma(mk0, wlo, acc0[2*jj]);
            acc0[2*jj+1] = f2fma(mk0, whi, acc0[2*jj+1]);
            acc1[2*jj]   = f2fma(mk1, wlo, acc1[2*jj]);
            acc1[2*jj+1] = f2fma(mk1, whi, acc1[2*jj+1]);
        }
    }

    const float bgv = __ldg(bg);
    // phase 3: silu, gate, vectorized reduction into g_agg
#pragma unroll
    for (int p = 0; p < 2; ++p) {
        float m2v[16];
        float gd = 0.f;
#pragma unroll
        for (int jj = 0; jj < 8; ++jj) {
            float lo, hi;
            upk2(p ? acc1[jj] : acc0[jj], lo, hi);
            lo = silu_f(lo); hi = silu_f(hi);
            m2v[2*jj] = lo; m2v[2*jj+1] = hi;
            gd += lo * sg[q * 16 + 2 * jj] + hi * sg[q * 16 + 2 * jj + 1];
        }
        gd += __shfl_xor_sync(0xffffffffu, gd, 1);
        gd += __shfl_xor_sync(0xffffffffu, gd, 2);
        float gate = sigmoid_f(gd + bgv);
        float* ag = g_agg + rbs[p] * 64 + q * 16;
#pragma unroll
        for (int jj = 0; jj < 4; ++jj) {
            asm volatile("red.global.add.v4.f32 [%0], {%1,%2,%3,%4};" ::
                "l"(ag + 4 * jj),
                "f"(gate * m2v[4*jj]),   "f"(gate * m2v[4*jj+1]),
                "f"(gate * m2v[4*jj+2]), "f"(gate * m2v[4*jj+3]) : "memory");
        }
    }
}

// ---------------------------------------------------------------------------
// Kernel 6: node update, 4 lanes per node, 64 nodes per block.
// ---------------------------------------------------------------------------
__global__ void __launch_bounds__(256) k_node(const float* __restrict__ Wn1,
                                              const float* __restrict__ bn1,
                                              const float* __restrict__ Wn2,
                                              const float* __restrict__ bn2,
                                              float* __restrict__ out) {
    extern __shared__ float sm[];
    float* sW1  = sm;                    // 8192
    float* sW2n = sm + 8192;             // 4096
    float* sx   = sm + 12288;            // 64*132 = 8448
    float* su   = sm + 12288 + 8448;     // 64*68 = 4352
    float* sb1  = su + 4352;             // 64
    float* sb2n = sb1 + 64;              // 64
    const int tid = threadIdx.x;
    for (int i = tid; i < 8192; i += 256) sW1[i] = Wn1[i];
    for (int i = tid; i < 4096; i += 256) sW2n[i] = Wn2[i];
    if (tid < 64) { sb1[tid] = bn1[tid]; sb2n[tid] = bn2[tid]; }

    const int q = tid & 3, s = tid >> 2;
    const int n = blockIdx.x * 64 + s;

    float4 hv[4];
    {
        const float4* hp = (const float4*)(g_hnew + n * 64 + q * 16);
        const float4* gp = (const float4*)(g_agg + n * 64 + q * 16);
        float4* sxh = (float4*)(sx + s * 132 + q * 16);
        float4* sxa = (float4*)(sx + s * 132 + 64 + q * 16);
#pragma unroll
        for (int jj = 0; jj < 4; ++jj) {
            hv[jj] = hp[jj];
            sxh[jj] = hv[jj];
            sxa[jj] = gp[jj];
        }
    }
    __syncthreads();

    // layer 1 over 128 inputs
    ull accU[8];
#pragma unroll
    for (int jj = 0; jj < 8; ++jj)
        accU[jj] = pk2(sb1[q * 16 + 2 * jj], sb1[q * 16 + 2 * jj + 1]);
    const float* xr = sx + s * 132;
#pragma unroll 4
    for (int k = 0; k < 128; ++k) {
        float mv = xr[k];
        ull mk = pk2(mv, mv);
        const float4* wr = (const float4*)(sW1 + k * 64 + q * 16);
#pragma unroll
        for (int jj = 0; jj < 4; ++jj) {
            float4 w = wr[jj];
            accU[2*jj]   = f2fma(mk, pk2(w.x, w.y), accU[2*jj]);
            accU[2*jj+1] = f2fma(mk, pk2(w.z, w.w), accU[2*jj+1]);
        }
    }
    {
        float4* sup = (float4*)(su + s * 68 + q * 16);
#pragma unroll
        for (int jj = 0; jj < 4; ++jj) {
            float4 v;
            upk2(accU[2*jj],   v.x, v.y);
            upk2(accU[2*jj+1], v.z, v.w);
            v.x = silu_f(v.x); v.y = silu_f(v.y);
            v.z = silu_f(v.z); v.w = silu_f(v.w);
            sup[jj] = v;
        }
    }
    __syncthreads();

    // layer 2 over 64 inputs
    ull acc2[8];
#pragma unroll
    for (int jj = 0; jj < 8; ++jj)
        acc2[jj] = pk2(sb2n[q * 16 + 2 * jj], sb2n[q * 16 + 2 * jj + 1]);
    const float* ur = su + s * 68;
#pragma unroll 4
    for (int k = 0; k < 64; ++k) {
        float mv = ur[k];
        ull mk = pk2(mv, mv);
        const float4* wr = (const float4*)(sW2n + k * 64 + q * 16);
#pragma unroll
        for (int jj = 0; jj < 4; ++jj) {
            float4 w = wr[jj];
            acc2[2*jj]   = f2fma(mk, pk2(w.x, w.y), acc2[2*jj]);
            acc2[2*jj+1] = f2fma(mk, pk2(w.z, w.w), acc2[2*jj+1]);
        }
    }
    float4* op = (float4*)(out + (size_t)n * 64 + q * 16);
#pragma unroll
    for (int jj = 0; jj < 4; ++jj) {
        float4 v;
        upk2(acc2[2*jj],   v.x, v.y);
        upk2(acc2[2*jj+1], v.z, v.w);
        v.x += hv[jj].x; v.y += hv[jj].y; v.z += hv[jj].z; v.w += hv[jj].w;
        op[jj] = v;
    }
}

// ---------------------------------------------------------------------------
extern "C" void kernel_launch(void* const* d_in, const int* in_sizes, int n_in,
                              void* d_out, int out_size) {
    const float* h   = (const float*)d_in[0];
    const float* x   = (const float*)d_in[1];
    const float* vel = (const float*)d_in[2];
    const int*   ei  = (const int*)d_in[3];
    const float* whr = (const float*)d_in[4];
    const float* whi = (const float*)d_in[5];
    const float* wvr = (const float*)d_in[6];
    const float* wvi = (const float*)d_in[7];
    const float* We1 = (const float*)d_in[8];
    const float* be1 = (const float*)d_in[9];
    const float* We2 = (const float*)d_in[10];
    const float* be2 = (const float*)d_in[11];
    const float* Wg  = (const float*)d_in[12];
    const float* bg  = (const float*)d_in[13];
    const float* Wn1 = (const float*)d_in[14];
    const float* bn1 = (const float*)d_in[15];
    const float* Wn2 = (const float*)d_in[16];
    const float* bn2 = (const float*)d_in[17];
    float* out = (float*)d_out;

    (void)in_sizes; (void)n_in; (void)out_size;

    const int smem_h    = 26112 * 4;                       // 104448 B
    const int smem_ab   = (8192 + 4352 + 64) * 4;          // 50432 B
    const int smem_edge = (4096 + 8704 + 192) * 4;         // 51968 B
    const int smem_node = (8192 + 4096 + 8448 + 4352 + 128) * 4; // 100864 B
    static bool attr_done = false;
    cudaFuncSetAttribute(k_time_h, cudaFuncAttributeMaxDynamicSharedMemorySize, smem_h);
    cudaFuncSetAttribute(k_ab,     cudaFuncAttributeMaxDynamicSharedMemorySize, smem_ab);
    cudaFuncSetAttribute(k_edge,   cudaFuncAttributeMaxDynamicSharedMemorySize, smem_edge);
    cudaFuncSetAttribute(k_node,   cudaFuncAttributeMaxDynamicSharedMemorySize, smem_node);
    (void)attr_done;

    // 1) time conv on h -> g_hnew
    k_time_h<<<625, 256, smem_h>>>(h, whr, whi);
    // 2) velocity conv -> d_out tail
    k_time_v<<<(BN_ * 3 + 255) / 256, 256>>>(vel, wvr, wvi, out + HTOT_);
    // 3) edge squared distances
    k_d2<<<(E_ + 255) / 256, 256>>>(x, ei);
    // 4) per-node A/B precompute + agg zero
    k_ab<<<NTOT_ / 64, 256, smem_ab>>>(We1, be1);
    // 5) edge messages + vector-red aggregate (10000 blocks, 1250 per t-slice)
    k_edge<<<(T_ * E_) / 128, 256, smem_edge>>>(ei, We1, We2, be2, Wg, bg);
    // 6) node update -> d_out head
    k_node<<<NTOT_ / 64, 256, smem_node>>>(Wn1, bn1, Wn2, bn2, out);
}

// round 4
// speedup vs baseline: 1.9913x; 1.9913x over previous
#include <cuda_runtime.h>

// Problem constants
#define BN_   10000
#define T_    8
#define C_    64
#define NM_   3
#define E_    160000
#define NTOT_ (T_ * BN_)        // 80000 node-rows
#define HTOT_ (NTOT_ * C_)      // 5,120,000

// Scratch (device globals: allocation-free rule)
__device__ __align__(16) float g_hnew[HTOT_];
__device__ __align__(16) float g_A[HTOT_];
__device__ __align__(16) float g_B[HTOT_];
__device__ __align__(16) float g_agg[HTOT_];
__device__ __align__(16) float g_d2[E_];

__constant__ float CT8[8] = {1.f,  0.70710678118654752f, 0.f, -0.70710678118654752f,
                             -1.f, -0.70710678118654752f, 0.f,  0.70710678118654752f};
__constant__ float ST8[8] = {0.f,  0.70710678118654752f, 1.f,  0.70710678118654752f,
                             0.f, -0.70710678118654752f, -1.f, -0.70710678118654752f};

typedef unsigned long long ull;

__device__ __forceinline__ float silu_f(float x)    { return x / (1.f + __expf(-x)); }
__device__ __forceinline__ float sigmoid_f(float x) { return 1.f / (1.f + __expf(-x)); }

__device__ __forceinline__ ull pk2(float lo, float hi) {
    ull r; asm("mov.b64 %0,{%1,%2};" : "=l"(r) : "f"(lo), "f"(hi)); return r;
}
__device__ __forceinline__ void upk2(ull v, float& lo, float& hi) {
    asm("mov.b64 {%0,%1},%2;" : "=f"(lo), "=f"(hi) : "l"(v));
}
__device__ __forceinline__ ull f2fma(ull a, ull b, ull c) {
    ull d; asm("fma.rn.f32x2 %0,%1,%2,%3;" : "=l"(d) : "l"(a), "l"(b), "l"(c)); return d;
}

// ---------------------------------------------------------------------------
// Kernel 1: TimeConv on h.  8 nodes/block, 2 nodes per phase-B thread.
// Complex mixing packed as f32x2 over modes (1,2); mode-0 scalar (imag of DC
// is discarded by irfft, numpy semantics).
// ---------------------------------------------------------------------------
__global__ void __launch_bounds__(256) k_time_h(const float* __restrict__ h,
                                                const float* __restrict__ whr,
                                                const float* __restrict__ whi) {
    extern __shared__ float sm[];
    float* sWr12 = sm;            // [i*64+o]*2 : (wr1, wr2)
    float* sWi12 = sm + 8192;     // (wi1, wi2)
    float* sWr0  = sm + 16384;    // wr0
    float* sxf   = sm + 20480;    // [8 slot][64 i][8]: xr1,xr2, xi1,xi2, -xi1,-xi2, xr0, pad
    const int tid = threadIdx.x;

    for (int idx = tid; idx < 4096; idx += 256) {
        int base = idx * 3;                  // (i*64+o)*3
        sWr12[idx * 2]     = whr[base + 1];
        sWr12[idx * 2 + 1] = whr[base + 2];
        sWi12[idx * 2]     = whi[base + 1];
        sWi12[idx * 2 + 1] = whi[base + 2];
        sWr0[idx]          = whr[base];
    }

    const int grp = tid >> 6;
    const int l   = tid & 63;
    const int node0 = blockIdx.x * 8 + grp * 2;

    // Phase A: rfft per (node, channel=l)
#pragma unroll
    for (int pp = 0; pp < 2; ++pp) {
        int node = node0 + pp;
        float xv[8];
#pragma unroll
        for (int t = 0; t < 8; ++t) xv[t] = h[t * (BN_ * C_) + node * C_ + l];
        float xr0 = 0.f, xr1 = 0.f, xi1 = 0.f, xr2 = 0.f, xi2 = 0.f;
#pragma unroll
        for (int t = 0; t < 8; ++t) {
            xr0 += xv[t];
            xr1 += xv[t] * CT8[t];
            xi1 -= xv[t] * ST8[t];
            xr2 += xv[t] * CT8[(2 * t) & 7];
            xi2 -= xv[t] * ST8[(2 * t) & 7];
        }
        float* p = sxf + (grp * 2 + pp) * 512 + l * 8;
        p[0] = xr1;  p[1] = xr2;
        p[2] = xi1;  p[3] = xi2;
        p[4] = -xi1; p[5] = -xi2;
        p[6] = xr0;  p[7] = 0.f;
    }
    __syncthreads();

    // Phase B: complex mix for o = l, 2 nodes
    ull omrA = pk2(0.f, 0.f), omiA = omrA, omrB = omrA, omiB = omrA;
    float om0A = 0.f, om0B = 0.f;
    const float* xA = sxf + grp * 1024;
    const float* xB = xA + 512;
#pragma unroll 4
    for (int i = 0; i < 64; ++i) {
        ull wr12 = *(const ull*)(sWr12 + (i * 64 + l) * 2);
        ull wi12 = *(const ull*)(sWi12 + (i * 64 + l) * 2);
        float wr0 = sWr0[i * 64 + l];
        const float* pa = xA + i * 8;
        const float* pb = xB + i * 8;
        ull xra = *(const ull*)pa;
        ull xia = *(const ull*)(pa + 2);
        ull nxa = *(const ull*)(pa + 4);
        ull xrb = *(const ull*)pb;
        ull xib = *(const ull*)(pb + 2);
        ull nxb = *(const ull*)(pb + 4);
        omrA = f2fma(xra, wr12, omrA); omrA = f2fma(nxa, wi12, omrA);
        omiA = f2fma(xra, wi12, omiA); omiA = f2fma(xia, wr12, omiA);
        om0A = fmaf(pa[6], wr0, om0A);
        omrB = f2fma(xrb, wr12, omrB); omrB = f2fma(nxb, wi12, omrB);
        omiB = f2fma(xrb, wi12, omiB); omiB = f2fma(xib, wr12, omiB);
        om0B = fmaf(pb[6], wr0, om0B);
    }

    // Phase C: irfft + leaky residual
#pragma unroll
    for (int pp = 0; pp < 2; ++pp) {
        int node = node0 + pp;
        float or1, or2, oi1, oi2, o0;
        if (pp == 0) { upk2(omrA, or1, or2); upk2(omiA, oi1, oi2); o0 = om0A; }
        else         { upk2(omrB, or1, or2); upk2(omiB, oi1, oi2); o0 = om0B; }
#pragma unroll
        for (int t = 0; t < 8; ++t) {
            float val = o0
                + 2.f * (or1 * CT8[t]           - oi1 * ST8[t])
                + 2.f * (or2 * CT8[(2 * t) & 7] - oi2 * ST8[(2 * t) & 7]);
            val *= 0.125f;
            float lr = val > 0.f ? val : 0.2f * val;
            int off = t * (BN_ * C_) + node * C_ + l;
            g_hnew[off] = h[off] + lr;
        }
    }
}

// ---------------------------------------------------------------------------
// Kernel 2: TimeConvX on velocity
// ---------------------------------------------------------------------------
__global__ void k_time_v(const float* __restrict__ vel,
                         const float* __restrict__ wvr,
                         const float* __restrict__ wvi,
                         float* __restrict__ out) {
    int j = blockIdx.x * blockDim.x + threadIdx.x;
    if (j >= BN_ * 3) return;
    int b = j / 3, d = j - b * 3;
    float xv[8];
#pragma unroll
    for (int t = 0; t < 8; ++t) xv[t] = vel[b * (T_ * 3) + t * 3 + d];
    float xr0 = 0.f, xr1 = 0.f, xi1 = 0.f, xr2 = 0.f, xi2 = 0.f;
#pragma unroll
    for (int t = 0; t < 8; ++t) {
        xr0 += xv[t];
        xr1 += xv[t] * CT8[t];
        xi1 -= xv[t] * ST8[t];
        xr2 += xv[t] * CT8[(2 * t) & 7];
        xi2 -= xv[t] * ST8[(2 * t) & 7];
    }
    float w0r = wvr[0];
    float w1r = wvr[1], w1i = wvi[1];
    float w2r = wvr[2], w2i = wvi[2];
    float yr0 = xr0 * w0r;
    float yr1 = xr1 * w1r - xi1 * w1i;
    float yi1 = xr1 * w1i + xi1 * w1r;
    float yr2 = xr2 * w2r - xi2 * w2i;
    float yi2 = xr2 * w2i + xi2 * w2r;
#pragma unroll
    for (int t = 0; t < 8; ++t) {
        float val = 0.125f * (yr0
            + 2.f * (yr1 * CT8[t]           - yi1 * ST8[t])
            + 2.f * (yr2 * CT8[(2 * t) & 7] - yi2 * ST8[(2 * t) & 7]));
        out[b * (T_ * 3) + t * 3 + d] = xv[t] + val;
    }
}

// ---------------------------------------------------------------------------
// Kernel 3: per-base-edge squared distance
// ---------------------------------------------------------------------------
__global__ void k_d2(const float* __restrict__ x, const int* __restrict__ ei) {
    int e = blockIdx.x * blockDim.x + threadIdx.x;
    if (e >= E_) return;
    int r = ei[e];
    int c = ei[E_ + e];
    float dx = x[r * 3 + 0] - x[c * 3 + 0];
    float dy = x[r * 3 + 1] - x[c * 3 + 1];
    float dz = x[r * 3 + 2] - x[c * 3 + 2];
    g_d2[e] = dx * dx + dy * dy + dz * dz;
}

// ---------------------------------------------------------------------------
// Kernel 4: A/B precompute as register-tiled GEMM.
// M=64 nodes/block, N=128 (A|B), K=64. 256 thr, thread tile 4m x 8n.
// ---------------------------------------------------------------------------
__global__ void __launch_bounds__(256) k_ab(const float* __restrict__ We1,
                                            const float* __restrict__ be1) {
    extern __shared__ float sm[];
    float* sX = sm;              // [64][68]
    float* sW = sm + 4352;       // [64][132]  n<64 -> We1 rows 0..63, else rows 64..127
    float* sbias = sm + 12800;   // [128]
    const int tid = threadIdx.x;

    for (int idx = tid; idx < 8192; idx += 256) {
        int k = idx >> 7, n = idx & 127;
        float v = (n < 64) ? We1[k * 64 + n] : We1[(64 + k) * 64 + (n - 64)];
        sW[k * 132 + n] = v;
    }
    if (tid < 128) sbias[tid] = (tid < 64) ? be1[tid] : 0.f;

    const int nb = blockIdx.x * 64;
    {
        int row = tid >> 2, l4 = tid & 3;
        const float4* hp = (const float4*)(g_hnew + (size_t)(nb + row) * 64 + l4 * 16);
        float4* agp = (float4*)(g_agg + (size_t)(nb + row) * 64 + l4 * 16);
        float4* sx4 = (float4*)(sX + row * 68 + l4 * 16);
        float4 z = make_float4(0.f, 0.f, 0.f, 0.f);
#pragma unroll
        for (int jj = 0; jj < 4; ++jj) { sx4[jj] = hp[jj]; agp[jj] = z; }
    }
    __syncthreads();

    const int lane = tid & 31, w = tid >> 5;
    const int mw = w & 1, nw = w >> 1;         // nw 0..3
    const int mq = lane >> 2, nq = lane & 3;
    const int m0 = mw * 32 + mq;               // + i*8
    const int nbase = nw * 32 + nq * 4;        // + 16j

    ull acc[16];
#pragma unroll
    for (int i = 0; i < 4; ++i)
#pragma unroll
        for (int jj = 0; jj < 2; ++jj) {
            int n0 = nbase + 16 * jj;
            acc[i * 4 + jj * 2]     = pk2(sbias[n0],     sbias[n0 + 1]);
            acc[i * 4 + jj * 2 + 1] = pk2(sbias[n0 + 2], sbias[n0 + 3]);
        }

    const float* xp = sX + m0 * 68;
#pragma unroll 2
    for (int k4 = 0; k4 < 16; ++k4) {
        float xa[4][4];
#pragma unroll
        for (int i = 0; i < 4; ++i) {
            float4 v = *(const float4*)(xp + i * 8 * 68 + k4 * 4);
            xa[i][0] = v.x; xa[i][1] = v.y; xa[i][2] = v.z; xa[i][3] = v.w;
        }
#pragma unroll
        for (int kk = 0; kk < 4; ++kk) {
            const float* wrow = sW + (k4 * 4 + kk) * 132 + nbase;
            ull wv[4];
            wv[0] = *(const ull*)(wrow);
            wv[1] = *(const ull*)(wrow + 2);
            wv[2] = *(const ull*)(wrow + 16);
            wv[3] = *(const ull*)(wrow + 18);
#pragma unroll
            for (int i = 0; i < 4; ++i) {
                ull mk = pk2(xa[i][kk], xa[i][kk]);
#pragma unroll
                for (int jj = 0; jj < 4; ++jj)
                    acc[i * 4 + jj] = f2fma(mk, wv[jj], acc[i * 4 + jj]);
            }
        }
    }

#pragma unroll
    for (int i = 0; i < 4; ++i) {
        int node = nb + m0 + i * 8;
#pragma unroll
        for (int jj = 0; jj < 2; ++jj) {
            int n0 = nbase + 16 * jj;
            float4 v;
            upk2(acc[i * 4 + jj * 2],     v.x, v.y);
            upk2(acc[i * 4 + jj * 2 + 1], v.z, v.w);
            if (n0 < 64) *(float4*)(g_A + (size_t)node * 64 + n0) = v;
            else         *(float4*)(g_B + (size_t)node * 64 + (n0 - 64)) = v;
        }
    }
}

// ---------------------------------------------------------------------------
// Kernel 5: edge messages. 256 edges/block.
// Phase1: gather m1 = silu(A[rb]+B[cb]+d2*wl) -> smem (4 lanes/edge).
// Phase2: register-tiled GEMM m2 = m1 @ We2 + b_e2 (warp tile 32m x 64n,
//         thread tile 4m x 16n, f32x2 acc).
// Phase3: silu, gate dot (shfl over quad), red.global.add.v4.
// ---------------------------------------------------------------------------
__global__ void __launch_bounds__(256) k_edge(const int* __restrict__ ei,
                                              const float* __restrict__ We1,
                                              const float* __restrict__ We2,
                                              const float* __restrict__ be2,
                                              const float* __restrict__ Wg,
                                              const float* __restrict__ bg) {
    extern __shared__ float sm[];
    float* sm1 = sm;                    // [256][68]
    float* sW2 = sm + 17408;            // [64][68]
    float* swl = sm + 21760;            // [64]
    float* sg  = sm + 21824;            // [64]
    float* sb2 = sm + 21888;            // [64]
    int*   srb = (int*)(sm + 21952);    // [256]
    const int tid = threadIdx.x;

    for (int idx = tid; idx < 4096; idx += 256)
        sW2[(idx >> 6) * 68 + (idx & 63)] = We2[idx];
    if (tid < 64) {
        swl[tid] = We1[128 * 64 + tid];
        sg[tid]  = Wg[tid];
        sb2[tid] = be2[tid];
    }
    // R3 BUG FIX: phase 1 reads swl staged above by other threads; must sync.
    __syncthreads();

    const int t  = blockIdx.x / 625;
    const int jb = (blockIdx.x - t * 625) * 256;

    // Phase 1
    {
        const int eIdx = tid >> 2, l4 = tid & 3;
#pragma unroll
        for (int p = 0; p < 4; ++p) {
            int e = p * 64 + eIdx;
            int j = jb + e;
            int rb = t * BN_ + __ldg(ei + j);
            int cb = t * BN_ + __ldg(ei + E_ + j);
            if (l4 == 0) srb[e] = rb;
            float dd = g_d2[j];
            const float4* Ap = (const float4*)(g_A + (size_t)rb * 64 + l4 * 16);
            const float4* Bp = (const float4*)(g_B + (size_t)cb * 64 + l4 * 16);
            const float4* wl = (const float4*)(swl + l4 * 16);
            float4* dst = (float4*)(sm1 + e * 68 + l4 * 16);
#pragma unroll
            for (int jj = 0; jj < 4; ++jj) {
                float4 a = Ap[jj], b = Bp[jj], ww = wl[jj];
                float4 o;
                o.x = silu_f(a.x + b.x + dd * ww.x);
                o.y = silu_f(a.y + b.y + dd * ww.y);
                o.z = silu_f(a.z + b.z + dd * ww.z);
                o.w = silu_f(a.w + b.w + dd * ww.w);
                dst[jj] = o;
            }
        }
    }
    __syncthreads();

    // Phase 2: GEMM  (warp w: edges w*32..w*32+31, all 64 outputs)
    const int lane = tid & 31, w = tid >> 5;
    const int mq = lane >> 2, nq = lane & 3;
    const int m0 = w * 32 + mq;                 // + i*8
    const int nbq = nq * 4;                     // + 16j

    ull acc[32];
#pragma unroll
    for (int i = 0; i < 4; ++i)
#pragma unroll
        for (int j = 0; j < 4; ++j) {
            int n0 = nbq + 16 * j;
            acc[i * 8 + j * 2]     = pk2(sb2[n0],     sb2[n0 + 1]);
            acc[i * 8 + j * 2 + 1] = pk2(sb2[n0 + 2], sb2[n0 + 3]);
        }

    const float* xp = sm1 + m0 * 68;
#pragma unroll 1
    for (int k4 = 0; k4 < 16; ++k4) {
        float xa[4][4];
#pragma unroll
        for (int i = 0; i < 4; ++i) {
            float4 v = *(const float4*)(xp + i * 8 * 68 + k4 * 4);
            xa[i][0] = v.x; xa[i][1] = v.y; xa[i][2] = v.z; xa[i][3] = v.w;
        }
#pragma unroll
        for (int kk = 0; kk < 4; ++kk) {
            const float* wrow = sW2 + (k4 * 4 + kk) * 68 + nbq;
            ull wv[8];
#pragma unroll
            for (int j = 0; j < 4; ++j) {
                wv[2 * j]     = *(const ull*)(wrow + 16 * j);
                wv[2 * j + 1] = *(const ull*)(wrow + 16 * j + 2);
            }
#pragma unroll
            for (int i = 0; i < 4; ++i) {
                ull mk = pk2(xa[i][kk], xa[i][kk]);
#pragma unroll
                for (int jj = 0; jj < 8; ++jj)
                    acc[i * 8 + jj] = f2fma(mk, wv[jj], acc[i * 8 + jj]);
            }
        }
    }

    // Phase 3
    const float bgv = __ldg(bg);
#pragma unroll
    for (int i = 0; i < 4; ++i) {
        int m = m0 + i * 8;
        float v[16];
        float gp = 0.f;
#pragma unroll
        for (int j = 0; j < 4; ++j) {
            int n0 = nbq + 16 * j;
            float a, b, c, d;
            upk2(acc[i * 8 + j * 2],     a, b);
            upk2(acc[i * 8 + j * 2 + 1], c, d);
            a = silu_f(a); b = silu_f(b); c = silu_f(c); d = silu_f(d);
            v[j * 4] = a; v[j * 4 + 1] = b; v[j * 4 + 2] = c; v[j * 4 + 3] = d;
            gp += a * sg[n0] + b * sg[n0 + 1] + c * sg[n0 + 2] + d * sg[n0 + 3];
        }
        gp += __shfl_xor_sync(0xffffffffu, gp, 1);
        gp += __shfl_xor_sync(0xffffffffu, gp, 2);
        float gate = sigmoid_f(gp + bgv);
        float* ag = g_agg + (size_t)srb[m] * 64 + nbq;
#pragma unroll
        for (int j = 0; j < 4; ++j) {
            asm volatile("red.global.add.v4.f32 [%0], {%1,%2,%3,%4};" ::
                "l"(ag + 16 * j),
                "f"(gate * v[j * 4]),     "f"(gate * v[j * 4 + 1]),
                "f"(gate * v[j * 4 + 2]), "f"(gate * v[j * 4 + 3]) : "memory");
        }
    }
}

// ---------------------------------------------------------------------------
// Kernel 6: node update as two register-tiled GEMMs.
// M=64 nodes/block, layer1 K=128, layer2 K=64, N=64.
// Warp tile 16m x 32n, thread tile 2m x 8n.
// ---------------------------------------------------------------------------
__global__ void __launch_bounds__(256) k_node(const float* __restrict__ Wn1,
                                              const float* __restrict__ bn1,
                                              const float* __restrict__ Wn2,
                                              const float* __restrict__ bn2,
                                              float* __restrict__ out) {
    extern __shared__ float sm[];
    float* sX  = sm;            // [64][132] = [h | agg]
    float* sW1 = sm + 8448;     // [128][68]
    float* sU  = sm + 17152;    // [64][68]
    float* sW2 = sm + 21504;    // [64][68]
    float* sb1 = sm + 25856;    // [64]
    float* sb2 = sm + 25920;    // [64]
    const int tid = threadIdx.x;

    for (int idx = tid; idx < 8192; idx += 256)
        sW1[(idx >> 6) * 68 + (idx & 63)] = Wn1[idx];
    for (int idx = tid; idx < 4096; idx += 256)
        sW2[(idx >> 6) * 68 + (idx & 63)] = Wn2[idx];
    if (tid < 64) { sb1[tid] = bn1[tid]; sb2[tid] = bn2[tid]; }

    const int nb = blockIdx.x * 64;
    {
        int row = tid >> 2, l4 = tid & 3;
        const float4* hp = (const float4*)(g_hnew + (size_t)(nb + row) * 64 + l4 * 16);
        const float4* gp = (const float4*)(g_agg  + (size_t)(nb + row) * 64 + l4 * 16);
        float4* sxh = (float4*)(sX + row * 132 + l4 * 16);
        float4* sxa = (float4*)(sX + row * 132 + 64 + l4 * 16);
#pragma unroll
        for (int jj = 0; jj < 4; ++jj) { sxh[jj] = hp[jj]; sxa[jj] = gp[jj]; }
    }
    __syncthreads();

    const int lane = tid & 31, w = tid >> 5;
    const int mw = w & 3, nw = w >> 2;          // nw 0..1
    const int mq = lane >> 2, nq = lane & 3;
    const int m0 = mw * 16 + mq;                // + i*8, i 0..1
    const int nbase = nw * 32 + nq * 4;         // + 16j, j 0..1

    // ---- layer 1 (K = 128) ----
    ull acc[8];
#pragma unroll
    for (int i = 0; i < 2; ++i)
#pragma unroll
        for (int jj = 0; jj < 2; ++jj) {
            int n0 = nbase + 16 * jj;
            acc[i * 4 + jj * 2]     = pk2(sb1[n0],     sb1[n0 + 1]);
            acc[i * 4 + jj * 2 + 1] = pk2(sb1[n0 + 2], sb1[n0 + 3]);
        }
    const float* xp = sX + m0 * 132;
#pragma unroll 2
    for (int k4 = 0; k4 < 32; ++k4) {
        float xa[2][4];
#pragma unroll
        for (int i = 0; i < 2; ++i) {
            float4 v = *(const float4*)(xp + i * 8 * 132 + k4 * 4);
            xa[i][0] = v.x; xa[i][1] = v.y; xa[i][2] = v.z; xa[i][3] = v.w;
        }
#pragma unroll
        for (int kk = 0; kk < 4; ++kk) {
            const float* wrow = sW1 + (k4 * 4 + kk) * 68 + nbase;
            ull wv[4];
            wv[0] = *(const ull*)(wrow);
            wv[1] = *(const ull*)(wrow + 2);
            wv[2] = *(const ull*)(wrow + 16);
            wv[3] = *(const ull*)(wrow + 18);
#pragma unroll
            for (int i = 0; i < 2; ++i) {
                ull mk = pk2(xa[i][kk], xa[i][kk]);
#pragma unroll
                for (int jj = 0; jj < 4; ++jj)
                    acc[i * 4 + jj] = f2fma(mk, wv[jj], acc[i * 4 + jj]);
            }
        }
    }
#pragma unroll
    for (int i = 0; i < 2; ++i) {
        int m = m0 + i * 8;
#pragma unroll
        for (int jj = 0; jj < 2; ++jj) {
            int n0 = nbase + 16 * jj;
            float4 v;
            upk2(acc[i * 4 + jj * 2],     v.x, v.y);
            upk2(acc[i * 4 + jj * 2 + 1], v.z, v.w);
            v.x = silu_f(v.x); v.y = silu_f(v.y);
            v.z = silu_f(v.z); v.w = silu_f(v.w);
            *(float4*)(sU + m * 68 + n0) = v;
        }
    }
    __syncthreads();

    // ---- layer 2 (K = 64) ----
    ull acc2[8];
#pragma unroll
    for (int i = 0; i < 2; ++i)
#pragma unroll
        for (int jj = 0; jj < 2; ++jj) {
            int n0 = nbase + 16 * jj;
            acc2[i * 4 + jj * 2]     = pk2(sb2[n0],     sb2[n0 + 1]);
            acc2[i * 4 + jj * 2 + 1] = pk2(sb2[n0 + 2], sb2[n0 + 3]);
        }
    const float* up = sU + m0 * 68;
#pragma unroll 2
    for (int k4 = 0; k4 < 16; ++k4) {
        float xa[2][4];
#pragma unroll
        for (int i = 0; i < 2; ++i) {
            float4 v = *(const float4*)(up + i * 8 * 68 + k4 * 4);
            xa[i][0] = v.x; xa[i][1] = v.y; xa[i][2] = v.z; xa[i][3] = v.w;
        }
#pragma unroll
        for (int kk = 0; kk < 4; ++kk) {
            const float* wrow = sW2 + (k4 * 4 + kk) * 68 + nbase;
            ull wv[4];
            wv[0] = *(const ull*)(wrow);
            wv[1] = *(const ull*)(wrow + 2);
            wv[2] = *(const ull*)(wrow + 16);
            wv[3] = *(const ull*)(wrow + 18);
#pragma unroll
            for (int i = 0; i < 2; ++i) {
                ull mk = pk2(xa[i][kk], xa[i][kk]);
#pragma unroll
                for (int jj = 0; jj < 4; ++jj)
                    acc2[i * 4 + jj] = f2fma(mk, wv[jj], acc2[i * 4 + jj]);
            }
        }
    }
    // residual + store
#pragma unroll
    for (int i = 0; i < 2; ++i) {
        int m = m0 + i * 8;
        int node = nb + m;
#pragma unroll
        for (int jj = 0; jj < 2; ++jj) {
            int n0 = nbase + 16 * jj;
            float4 v;
            upk2(acc2[i * 4 + jj * 2],     v.x, v.y);
            upk2(acc2[i * 4 + jj * 2 + 1], v.z, v.w);
            float4 hv = *(const float4*)(sX + m * 132 + n0);
            v.x += hv.x; v.y += hv.y; v.z += hv.z; v.w += hv.w;
            *(float4*)(out + (size_t)node * 64 + n0) = v;
        }
    }
}

// ---------------------------------------------------------------------------
extern "C" void kernel_launch(void* const* d_in, const int* in_sizes, int n_in,
                              void* d_out, int out_size) {
    const float* h   = (const float*)d_in[0];
    const float* x   = (const float*)d_in[1];
    const float* vel = (const float*)d_in[2];
    const int*   ei  = (const int*)d_in[3];
    const float* whr = (const float*)d_in[4];
    const float* whi = (const float*)d_in[5];
    const float* wvr = (const float*)d_in[6];
    const float* wvi = (const float*)d_in[7];
    const float* We1 = (const float*)d_in[8];
    const float* be1 = (const float*)d_in[9];
    const float* We2 = (const float*)d_in[10];
    const float* be2 = (const float*)d_in[11];
    const float* Wg  = (const float*)d_in[12];
    const float* bg  = (const float*)d_in[13];
    const float* Wn1 = (const float*)d_in[14];
    const float* bn1 = (const float*)d_in[15];
    const float* Wn2 = (const float*)d_in[16];
    const float* bn2 = (const float*)d_in[17];
    float* out = (float*)d_out;

    (void)in_sizes; (void)n_in; (void)out_size;

    const int smem_h    = 24576 * 4;  // 98304
    const int smem_ab   = 12928 * 4;  // 51712
    const int smem_edge = 22208 * 4;  // 88832
    const int smem_node = 25984 * 4;  // 103936
    cudaFuncSetAttribute(k_time_h, cudaFuncAttributeMaxDynamicSharedMemorySize, smem_h);
    cudaFuncSetAttribute(k_ab,     cudaFuncAttributeMaxDynamicSharedMemorySize, smem_ab);
    cudaFuncSetAttribute(k_edge,   cudaFuncAttributeMaxDynamicSharedMemorySize, smem_edge);
    cudaFuncSetAttribute(k_node,   cudaFuncAttributeMaxDynamicSharedMemorySize, smem_node);

    k_time_h<<<1250, 256, smem_h>>>(h, whr, whi);
    k_time_v<<<(BN_ * 3 + 255) / 256, 256>>>(vel, wvr, wvi, out + HTOT_);
    k_d2<<<(E_ + 255) / 256, 256>>>(x, ei);
    k_ab<<<1250, 256, smem_ab>>>(We1, be1);
    k_edge<<<5000, 256, smem_edge>>>(ei, We1, We2, be2, Wg, bg);
    k_node<<<1250, 256, smem_node>>>(Wn1, bn1, Wn2, bn2, out);
}

// round 6
// speedup vs baseline: 2.0326x; 1.0207x over previous
#include <cuda_runtime.h>

// Problem constants
#define BN_   10000
#define T_    8
#define C_    64
#define NM_   3
#define E_    160000
#define NTOT_ (T_ * BN_)        // 80000 node-rows
#define HTOT_ (NTOT_ * C_)      // 5,120,000

// Scratch (device globals: allocation-free rule)
__device__ __align__(16) float g_hnew[HTOT_];
__device__ __align__(16) float g_A[HTOT_];
__device__ __align__(16) float g_B[HTOT_];
__device__ __align__(16) float g_agg[HTOT_];
__device__ __align__(16) float g_d2[E_];

__constant__ float CT8[8] = {1.f,  0.70710678118654752f, 0.f, -0.70710678118654752f,
                             -1.f, -0.70710678118654752f, 0.f,  0.70710678118654752f};
__constant__ float ST8[8] = {0.f,  0.70710678118654752f, 1.f,  0.70710678118654752f,
                             0.f, -0.70710678118654752f, -1.f, -0.70710678118654752f};

typedef unsigned long long ull;

__device__ __forceinline__ float silu_f(float x)    { return x / (1.f + __expf(-x)); }
__device__ __forceinline__ float sigmoid_f(float x) { return 1.f / (1.f + __expf(-x)); }

__device__ __forceinline__ ull pk2(float lo, float hi) {
    ull r; asm("mov.b64 %0,{%1,%2};" : "=l"(r) : "f"(lo), "f"(hi)); return r;
}
__device__ __forceinline__ void upk2(ull v, float& lo, float& hi) {
    asm("mov.b64 {%0,%1},%2;" : "=f"(lo), "=f"(hi) : "l"(v));
}
__device__ __forceinline__ ull f2fma(ull a, ull b, ull c) {
    ull d; asm("fma.rn.f32x2 %0,%1,%2,%3;" : "=l"(d) : "l"(a), "l"(b), "l"(c)); return d;
}

// ---------------------------------------------------------------------------
// Kernel 1: TimeConv on h.  8 nodes/block, 2 nodes per phase-B thread.
// ---------------------------------------------------------------------------
__global__ void __launch_bounds__(256, 2) k_time_h(const float* __restrict__ h,
                                                   const float* __restrict__ whr,
                                                   const float* __restrict__ whi) {
    extern __shared__ float sm[];
    float* sWr12 = sm;            // [i*64+o]*2 : (wr1, wr2)
    float* sWi12 = sm + 8192;     // (wi1, wi2)
    float* sWr0  = sm + 16384;    // wr0
    float* sxf   = sm + 20480;    // [8 slot][64 i][8]
    const int tid = threadIdx.x;

    for (int idx = tid; idx < 4096; idx += 256) {
        int base = idx * 3;                  // (i*64+o)*3
        sWr12[idx * 2]     = whr[base + 1];
        sWr12[idx * 2 + 1] = whr[base + 2];
        sWi12[idx * 2]     = whi[base + 1];
        sWi12[idx * 2 + 1] = whi[base + 2];
        sWr0[idx]          = whr[base];
    }

    const int grp = tid >> 6;
    const int l   = tid & 63;
    const int node0 = blockIdx.x * 8 + grp * 2;

    // Phase A: rfft per (node, channel=l)
#pragma unroll
    for (int pp = 0; pp < 2; ++pp) {
        int node = node0 + pp;
        float xv[8];
#pragma unroll
        for (int t = 0; t < 8; ++t) xv[t] = h[t * (BN_ * C_) + node * C_ + l];
        float xr0 = 0.f, xr1 = 0.f, xi1 = 0.f, xr2 = 0.f, xi2 = 0.f;
#pragma unroll
        for (int t = 0; t < 8; ++t) {
            xr0 += xv[t];
            xr1 += xv[t] * CT8[t];
            xi1 -= xv[t] * ST8[t];
            xr2 += xv[t] * CT8[(2 * t) & 7];
            xi2 -= xv[t] * ST8[(2 * t) & 7];
        }
        float* p = sxf + (grp * 2 + pp) * 512 + l * 8;
        p[0] = xr1;  p[1] = xr2;
        p[2] = xi1;  p[3] = xi2;
        p[4] = -xi1; p[5] = -xi2;
        p[6] = xr0;  p[7] = 0.f;
    }
    __syncthreads();

    // Phase B: complex mix for o = l, 2 nodes
    ull omrA = pk2(0.f, 0.f), omiA = omrA, omrB = omrA, omiB = omrA;
    float om0A = 0.f, om0B = 0.f;
    const float* xA = sxf + grp * 1024;
    const float* xB = xA + 512;
#pragma unroll 4
    for (int i = 0; i < 64; ++i) {
        ull wr12 = *(const ull*)(sWr12 + (i * 64 + l) * 2);
        ull wi12 = *(const ull*)(sWi12 + (i * 64 + l) * 2);
        float wr0 = sWr0[i * 64 + l];
        const float* pa = xA + i * 8;
        const float* pb = xB + i * 8;
        ull xra = *(const ull*)pa;
        ull xia = *(const ull*)(pa + 2);
        ull nxa = *(const ull*)(pa + 4);
        ull xrb = *(const ull*)pb;
        ull xib = *(const ull*)(pb + 2);
        ull nxb = *(const ull*)(pb + 4);
        omrA = f2fma(xra, wr12, omrA); omrA = f2fma(nxa, wi12, omrA);
        omiA = f2fma(xra, wi12, omiA); omiA = f2fma(xia, wr12, omiA);
        om0A = fmaf(pa[6], wr0, om0A);
        omrB = f2fma(xrb, wr12, omrB); omrB = f2fma(nxb, wi12, omrB);
        omiB = f2fma(xrb, wi12, omiB); omiB = f2fma(xib, wr12, omiB);
        om0B = fmaf(pb[6], wr0, om0B);
    }

    // Phase C: irfft + leaky residual
#pragma unroll
    for (int pp = 0; pp < 2; ++pp) {
        int node = node0 + pp;
        float or1, or2, oi1, oi2, o0;
        if (pp == 0) { upk2(omrA, or1, or2); upk2(omiA, oi1, oi2); o0 = om0A; }
        else         { upk2(omrB, or1, or2); upk2(omiB, oi1, oi2); o0 = om0B; }
#pragma unroll
        for (int t = 0; t < 8; ++t) {
            float val = o0
                + 2.f * (or1 * CT8[t]           - oi1 * ST8[t])
                + 2.f * (or2 * CT8[(2 * t) & 7] - oi2 * ST8[(2 * t) & 7]);
            val *= 0.125f;
            float lr = val > 0.f ? val : 0.2f * val;
            int off = t * (BN_ * C_) + node * C_ + l;
            g_hnew[off] = h[off] + lr;
        }
    }
}

// ---------------------------------------------------------------------------
// Kernel 2: TimeConvX on velocity
// ---------------------------------------------------------------------------
__global__ void k_time_v(const float* __restrict__ vel,
                         const float* __restrict__ wvr,
                         const float* __restrict__ wvi,
                         float* __restrict__ out) {
    int j = blockIdx.x * blockDim.x + threadIdx.x;
    if (j >= BN_ * 3) return;
    int b = j / 3, d = j - b * 3;
    float xv[8];
#pragma unroll
    for (int t = 0; t < 8; ++t) xv[t] = vel[b * (T_ * 3) + t * 3 + d];
    float xr0 = 0.f, xr1 = 0.f, xi1 = 0.f, xr2 = 0.f, xi2 = 0.f;
#pragma unroll
    for (int t = 0; t < 8; ++t) {
        xr0 += xv[t];
        xr1 += xv[t] * CT8[t];
        xi1 -= xv[t] * ST8[t];
        xr2 += xv[t] * CT8[(2 * t) & 7];
        xi2 -= xv[t] * ST8[(2 * t) & 7];
    }
    float w0r = wvr[0];
    float w1r = wvr[1], w1i = wvi[1];
    float w2r = wvr[2], w2i = wvi[2];
    float yr0 = xr0 * w0r;
    float yr1 = xr1 * w1r - xi1 * w1i;
    float yi1 = xr1 * w1i + xi1 * w1r;
    float yr2 = xr2 * w2r - xi2 * w2i;
    float yi2 = xr2 * w2i + xi2 * w2r;
#pragma unroll
    for (int t = 0; t < 8; ++t) {
        float val = 0.125f * (yr0
            + 2.f * (yr1 * CT8[t]           - yi1 * ST8[t])
            + 2.f * (yr2 * CT8[(2 * t) & 7] - yi2 * ST8[(2 * t) & 7]));
        out[b * (T_ * 3) + t * 3 + d] = xv[t] + val;
    }
}

// ---------------------------------------------------------------------------
// Kernel 3: per-base-edge squared distance
// ---------------------------------------------------------------------------
__global__ void k_d2(const float* __restrict__ x, const int* __restrict__ ei) {
    int e = blockIdx.x * blockDim.x + threadIdx.x;
    if (e >= E_) return;
    int r = ei[e];
    int c = ei[E_ + e];
    float dx = x[r * 3 + 0] - x[c * 3 + 0];
    float dy = x[r * 3 + 1] - x[c * 3 + 1];
    float dz = x[r * 3 + 2] - x[c * 3 + 2];
    g_d2[e] = dx * dx + dy * dy + dz * dz;
}

// ---------------------------------------------------------------------------
// Kernel 4: A/B precompute as register-tiled GEMM.
// M=64 nodes/block, N=128 (A|B), K=64. 256 thr, thread tile 4m x 8n.
// ---------------------------------------------------------------------------
__global__ void __launch_bounds__(256, 4) k_ab(const float* __restrict__ We1,
                                               const float* __restrict__ be1) {
    extern __shared__ float sm[];
    float* sX = sm;              // [64][68]
    float* sW = sm + 4352;       // [64][132]
    float* sbias = sm + 12800;   // [128]
    const int tid = threadIdx.x;

    for (int idx = tid; idx < 8192; idx += 256) {
        int k = idx >> 7, n = idx & 127;
        float v = (n < 64) ? We1[k * 64 + n] : We1[(64 + k) * 64 + (n - 64)];
        sW[k * 132 + n] = v;
    }
    if (tid < 128) sbias[tid] = (tid < 64) ? be1[tid] : 0.f;

    const int nb = blockIdx.x * 64;
    {
        int row = tid >> 2, l4 = tid & 3;
        const float4* hp = (const float4*)(g_hnew + (size_t)(nb + row) * 64 + l4 * 16);
        float4* agp = (float4*)(g_agg + (size_t)(nb + row) * 64 + l4 * 16);
        float4* sx4 = (float4*)(sX + row * 68 + l4 * 16);
        float4 z = make_float4(0.f, 0.f, 0.f, 0.f);
#pragma unroll
        for (int jj = 0; jj < 4; ++jj) { sx4[jj] = hp[jj]; agp[jj] = z; }
    }
    __syncthreads();

    const int lane = tid & 31, w = tid >> 5;
    const int mw = w & 1, nw = w >> 1;         // nw 0..3
    const int mq = lane >> 2, nq = lane & 3;
    const int m0 = mw * 32 + mq;               // + i*8
    const int nbase = nw * 32 + nq * 4;        // + 16j

    ull acc[16];
#pragma unroll
    for (int i = 0; i < 4; ++i)
#pragma unroll
        for (int jj = 0; jj < 2; ++jj) {
            int n0 = nbase + 16 * jj;
            acc[i * 4 + jj * 2]     = pk2(sbias[n0],     sbias[n0 + 1]);
            acc[i * 4 + jj * 2 + 1] = pk2(sbias[n0 + 2], sbias[n0 + 3]);
        }

    const float* xp = sX + m0 * 68;
#pragma unroll 2
    for (int k4 = 0; k4 < 16; ++k4) {
        float xa[4][4];
#pragma unroll
        for (int i = 0; i < 4; ++i) {
            float4 v = *(const float4*)(xp + i * 8 * 68 + k4 * 4);
            xa[i][0] = v.x; xa[i][1] = v.y; xa[i][2] = v.z; xa[i][3] = v.w;
        }
#pragma unroll
        for (int kk = 0; kk < 4; ++kk) {
            const float* wrow = sW + (k4 * 4 + kk) * 132 + nbase;
            ull wv[4];
            wv[0] = *(const ull*)(wrow);
            wv[1] = *(const ull*)(wrow + 2);
            wv[2] = *(const ull*)(wrow + 16);
            wv[3] = *(const ull*)(wrow + 18);
#pragma unroll
            for (int i = 0; i < 4; ++i) {
                ull mk = pk2(xa[i][kk], xa[i][kk]);
#pragma unroll
                for (int jj = 0; jj < 4; ++jj)
                    acc[i * 4 + jj] = f2fma(mk, wv[jj], acc[i * 4 + jj]);
            }
        }
    }

#pragma unroll
    for (int i = 0; i < 4; ++i) {
        int node = nb + m0 + i * 8;
#pragma unroll
        for (int jj = 0; jj < 2; ++jj) {
            int n0 = nbase + 16 * jj;
            float4 v;
            upk2(acc[i * 4 + jj * 2],     v.x, v.y);
            upk2(acc[i * 4 + jj * 2 + 1], v.z, v.w);
            if (n0 < 64) *(float4*)(g_A + (size_t)node * 64 + n0) = v;
            else         *(float4*)(g_B + (size_t)node * 64 + (n0 - 64)) = v;
        }
    }
}

// ---------------------------------------------------------------------------
// Kernel 5: edge messages. 256 edges/block. 2 blocks/SM for phase overlap.
// ---------------------------------------------------------------------------
__global__ void __launch_bounds__(256, 2) k_edge(const int* __restrict__ ei,
                                                 const float* __restrict__ We1,
                                                 const float* __restrict__ We2,
                                                 const float* __restrict__ be2,
                                                 const float* __restrict__ Wg,
                                                 const float* __restrict__ bg) {
    extern __shared__ float sm[];
    float* sm1 = sm;                    // [256][68]
    float* sW2 = sm + 17408;            // [64][68]
    float* swl = sm + 21760;            // [64]
    float* sg  = sm + 21824;            // [64]
    float* sb2 = sm + 21888;            // [64]
    int*   srb = (int*)(sm + 21952);    // [256]
    const int tid = threadIdx.x;

    for (int idx = tid; idx < 4096; idx += 256)
        sW2[(idx >> 6) * 68 + (idx & 63)] = We2[idx];
    if (tid < 64) {
        swl[tid] = We1[128 * 64 + tid];
        sg[tid]  = Wg[tid];
        sb2[tid] = be2[tid];
    }
    __syncthreads();

    const int t  = blockIdx.x / 625;
    const int jb = (blockIdx.x - t * 625) * 256;

    // Phase 1
    {
        const int eIdx = tid >> 2, l4 = tid & 3;
#pragma unroll
        for (int p = 0; p < 4; ++p) {
            int e = p * 64 + eIdx;
            int j = jb + e;
            int rb = t * BN_ + __ldg(ei + j);
            int cb = t * BN_ + __ldg(ei + E_ + j);
            if (l4 == 0) srb[e] = rb;
            float dd = g_d2[j];
            const float4* Ap = (const float4*)(g_A + (size_t)rb * 64 + l4 * 16);
            const float4* Bp = (const float4*)(g_B + (size_t)cb * 64 + l4 * 16);
            const float4* wl = (const float4*)(swl + l4 * 16);
            float4* dst = (float4*)(sm1 + e * 68 + l4 * 16);
#pragma unroll
            for (int jj = 0; jj < 4; ++jj) {
                float4 a = Ap[jj], b = Bp[jj], ww = wl[jj];
                float4 o;
                o.x = silu_f(a.x + b.x + dd * ww.x);
                o.y = silu_f(a.y + b.y + dd * ww.y);
                o.z = silu_f(a.z + b.z + dd * ww.z);
                o.w = silu_f(a.w + b.w + dd * ww.w);
                dst[jj] = o;
            }
        }
    }
    __syncthreads();

    // Phase 2: GEMM  (warp w: edges w*32..w*32+31, all 64 outputs)
    const int lane = tid & 31, w = tid >> 5;
    const int mq = lane >> 2, nq = lane & 3;
    const int m0 = w * 32 + mq;                 // + i*8
    const int nbq = nq * 4;                     // + 16j

    ull acc[32];
#pragma unroll
    for (int i = 0; i < 4; ++i)
#pragma unroll
        for (int j = 0; j < 4; ++j) {
            int n0 = nbq + 16 * j;
            acc[i * 8 + j * 2]     = pk2(sb2[n0],     sb2[n0 + 1]);
            acc[i * 8 + j * 2 + 1] = pk2(sb2[n0 + 2], sb2[n0 + 3]);
        }

    const float* xp = sm1 + m0 * 68;
#pragma unroll 1
    for (int k4 = 0; k4 < 16; ++k4) {
        float xa[4][4];
#pragma unroll
        for (int i = 0; i < 4; ++i) {
            float4 v = *(const float4*)(xp + i * 8 * 68 + k4 * 4);
            xa[i][0] = v.x; xa[i][1] = v.y; xa[i][2] = v.z; xa[i][3] = v.w;
        }
#pragma unroll
        for (int kk = 0; kk < 4; ++kk) {
            const float* wrow = sW2 + (k4 * 4 + kk) * 68 + nbq;
            ull wv[8];
#pragma unroll
            for (int j = 0; j < 4; ++j) {
                wv[2 * j]     = *(const ull*)(wrow + 16 * j);
                wv[2 * j + 1] = *(const ull*)(wrow + 16 * j + 2);
            }
#pragma unroll
            for (int i = 0; i < 4; ++i) {
                ull mk = pk2(xa[i][kk], xa[i][kk]);
#pragma unroll
                for (int jj = 0; jj < 8; ++jj)
                    acc[i * 8 + jj] = f2fma(mk, wv[jj], acc[i * 8 + jj]);
            }
        }
    }

    // Phase 3
    const float bgv = __ldg(bg);
#pragma unroll
    for (int i = 0; i < 4; ++i) {
        int m = m0 + i * 8;
        float v[16];
        float gp = 0.f;
#pragma unroll
        for (int j = 0; j < 4; ++j) {
            int n0 = nbq + 16 * j;
            float a, b, c, d;
            upk2(acc[i * 8 + j * 2],     a, b);
            upk2(acc[i * 8 + j * 2 + 1], c, d);
            a = silu_f(a); b = silu_f(b); c = silu_f(c); d = silu_f(d);
            v[j * 4] = a; v[j * 4 + 1] = b; v[j * 4 + 2] = c; v[j * 4 + 3] = d;
            gp += a * sg[n0] + b * sg[n0 + 1] + c * sg[n0 + 2] + d * sg[n0 + 3];
        }
        gp += __shfl_xor_sync(0xffffffffu, gp, 1);
        gp += __shfl_xor_sync(0xffffffffu, gp, 2);
        float gate = sigmoid_f(gp + bgv);
        float* ag = g_agg + (size_t)srb[m] * 64 + nbq;
#pragma unroll
        for (int j = 0; j < 4; ++j) {
            asm volatile("red.global.add.v4.f32 [%0], {%1,%2,%3,%4};" ::
                "l"(ag + 16 * j),
                "f"(gate * v[j * 4]),     "f"(gate * v[j * 4 + 1]),
                "f"(gate * v[j * 4 + 2]), "f"(gate * v[j * 4 + 3]) : "memory");
        }
    }
}

// ---------------------------------------------------------------------------
// Kernel 6: node update as two register-tiled GEMMs.
// ---------------------------------------------------------------------------
__global__ void __launch_bounds__(256, 2) k_node(const float* __restrict__ Wn1,
                                                 const float* __restrict__ bn1,
                                                 const float* __restrict__ Wn2,
                                                 const float* __restrict__ bn2,
                                                 float* __restrict__ out) {
    extern __shared__ float sm[];
    float* sX  = sm;            // [64][132] = [h | agg]
    float* sW1 = sm + 8448;     // [128][68]
    float* sU  = sm + 17152;    // [64][68]
    float* sW2 = sm + 21504;    // [64][68]
    float* sb1 = sm + 25856;    // [64]
    float* sb2 = sm + 25920;    // [64]
    const int tid = threadIdx.x;

    for (int idx = tid; idx < 8192; idx += 256)
        sW1[(idx >> 6) * 68 + (idx & 63)] = Wn1[idx];
    for (int idx = tid; idx < 4096; idx += 256)
        sW2[(idx >> 6) * 68 + (idx & 63)] = Wn2[idx];
    if (tid < 64) { sb1[tid] = bn1[tid]; sb2[tid] = bn2[tid]; }

    const int nb = blockIdx.x * 64;
    {
        int row = tid >> 2, l4 = tid & 3;
        const float4* hp = (const float4*)(g_hnew + (size_t)(nb + row) * 64 + l4 * 16);
        const float4* gp = (const float4*)(g_agg  + (size_t)(nb + row) * 64 + l4 * 16);
        float4* sxh = (float4*)(sX + row * 132 + l4 * 16);
        float4* sxa = (float4*)(sX + row * 132 + 64 + l4 * 16);
#pragma unroll
        for (int jj = 0; jj < 4; ++jj) { sxh[jj] = hp[jj]; sxa[jj] = gp[jj]; }
    }
    __syncthreads();

    const int lane = tid & 31, w = tid >> 5;
    const int mw = w & 3, nw = w >> 2;          // nw 0..1
    const int mq = lane >> 2, nq = lane & 3;
    const int m0 = mw * 16 + mq;                // + i*8, i 0..1
    const int nbase = nw * 32 + nq * 4;         // + 16j, j 0..1

    // ---- layer 1 (K = 128) ----
    ull acc[8];
#pragma unroll
    for (int i = 0; i < 2; ++i)
#pragma unroll
        for (int jj = 0; jj < 2; ++jj) {
            int n0 = nbase + 16 * jj;
            acc[i * 4 + jj * 2]     = pk2(sb1[n0],     sb1[n0 + 1]);
            acc[i * 4 + jj * 2 + 1] = pk2(sb1[n0 + 2], sb1[n0 + 3]);
        }
    const float* xp = sX + m0 * 132;
#pragma unroll 2
    for (int k4 = 0; k4 < 32; ++k4) {
        float xa[2][4];
#pragma unroll
        for (int i = 0; i < 2; ++i) {
            float4 v = *(const float4*)(xp + i * 8 * 132 + k4 * 4);
            xa[i][0] = v.x; xa[i][1] = v.y; xa[i][2] = v.z; xa[i][3] = v.w;
        }
#pragma unroll
        for (int kk = 0; kk < 4; ++kk) {
            const float* wrow = sW1 + (k4 * 4 + kk) * 68 + nbase;
            ull wv[4];
            wv[0] = *(const ull*)(wrow);
            wv[1] = *(const ull*)(wrow + 2);
            wv[2] = *(const ull*)(wrow + 16);
            wv[3] = *(const ull*)(wrow + 18);
#pragma unroll
            for (int i = 0; i < 2; ++i) {
                ull mk = pk2(xa[i][kk], xa[i][kk]);
#pragma unroll
                for (int jj = 0; jj < 4; ++jj)
                    acc[i * 4 + jj] = f2fma(mk, wv[jj], acc[i * 4 + jj]);
            }
        }
    }
#pragma unroll
    for (int i = 0; i < 2; ++i) {
        int m = m0 + i * 8;
#pragma unroll
        for (int jj = 0; jj < 2; ++jj) {
            int n0 = nbase + 16 * jj;
            float4 v;
            upk2(acc[i * 4 + jj * 2],     v.x, v.y);
            upk2(acc[i * 4 + jj * 2 + 1], v.z, v.w);
            v.x = silu_f(v.x); v.y = silu_f(v.y);
            v.z = silu_f(v.z); v.w = silu_f(v.w);
            *(float4*)(sU + m * 68 + n0) = v;
        }
    }
    __syncthreads();

    // ---- layer 2 (K = 64) ----
    ull acc2[8];
#pragma unroll
    for (int i = 0; i < 2; ++i)
#pragma unroll
        for (int jj = 0; jj < 2; ++jj) {
            int n0 = nbase + 16 * jj;
            acc2[i * 4 + jj * 2]     = pk2(sb2[n0],     sb2[n0 + 1]);
            acc2[i * 4 + jj * 2 + 1] = pk2(sb2[n0 + 2], sb2[n0 + 3]);
        }
    const float* up = sU + m0 * 68;
#pragma unroll 2
    for (int k4 = 0; k4 < 16; ++k4) {
        float xa[2][4];
#pragma unroll
        for (int i = 0; i < 2; ++i) {
            float4 v = *(const float4*)(up + i * 8 * 68 + k4 * 4);
            xa[i][0] = v.x; xa[i][1] = v.y; xa[i][2] = v.z; xa[i][3] = v.w;
        }
#pragma unroll
        for (int kk = 0; kk < 4; ++kk) {
            const float* wrow = sW2 + (k4 * 4 + kk) * 68 + nbase;
            ull wv[4];
            wv[0] = *(const ull*)(wrow);
            wv[1] = *(const ull*)(wrow + 2);
            wv[2] = *(const ull*)(wrow + 16);
            wv[3] = *(const ull*)(wrow + 18);
#pragma unroll
            for (int i = 0; i < 2; ++i) {
                ull mk = pk2(xa[i][kk], xa[i][kk]);
#pragma unroll
                for (int jj = 0; jj < 4; ++jj)
                    acc2[i * 4 + jj] = f2fma(mk, wv[jj], acc2[i * 4 + jj]);
            }
        }
    }
    // residual + store
#pragma unroll
    for (int i = 0; i < 2; ++i) {
        int m = m0 + i * 8;
        int node = nb + m;
#pragma unroll
        for (int jj = 0; jj < 2; ++jj) {
            int n0 = nbase + 16 * jj;
            float4 v;
            upk2(acc2[i * 4 + jj * 2],     v.x, v.y);
            upk2(acc2[i * 4 + jj * 2 + 1], v.z, v.w);
            float4 hv = *(const float4*)(sX + m * 132 + n0);
            v.x += hv.x; v.y += hv.y; v.z += hv.z; v.w += hv.w;
            *(float4*)(out + (size_t)node * 64 + n0) = v;
        }
    }
}

// ---------------------------------------------------------------------------
extern "C" void kernel_launch(void* const* d_in, const int* in_sizes, int n_in,
                              void* d_out, int out_size) {
    const float* h   = (const float*)d_in[0];
    const float* x   = (const float*)d_in[1];
    const float* vel = (const float*)d_in[2];
    const int*   ei  = (const int*)d_in[3];
    const float* whr = (const float*)d_in[4];
    const float* whi = (const float*)d_in[5];
    const float* wvr = (const float*)d_in[6];
    const float* wvi = (const float*)d_in[7];
    const float* We1 = (const float*)d_in[8];
    const float* be1 = (const float*)d_in[9];
    const float* We2 = (const float*)d_in[10];
    const float* be2 = (const float*)d_in[11];
    const float* Wg  = (const float*)d_in[12];
    const float* bg  = (const float*)d_in[13];
    const float* Wn1 = (const float*)d_in[14];
    const float* bn1 = (const float*)d_in[15];
    const float* Wn2 = (const float*)d_in[16];
    const float* bn2 = (const float*)d_in[17];
    float* out = (float*)d_out;

    (void)in_sizes; (void)n_in; (void)out_size;

    const int smem_h    = 24576 * 4;  // 98304
    const int smem_ab   = 12928 * 4;  // 51712
    const int smem_edge = 22208 * 4;  // 88832
    const int smem_node = 25984 * 4;  // 103936
    cudaFuncSetAttribute(k_time_h, cudaFuncAttributeMaxDynamicSharedMemorySize, smem_h);
    cudaFuncSetAttribute(k_ab,     cudaFuncAttributeMaxDynamicSharedMemorySize, smem_ab);
    cudaFuncSetAttribute(k_edge,   cudaFuncAttributeMaxDynamicSharedMemorySize, smem_edge);
    cudaFuncSetAttribute(k_node,   cudaFuncAttributeMaxDynamicSharedMemorySize, smem_node);

    // Launch order chosen so k_edge is the 4th launch (ncu capture slot),
    // dependency-safe: d2 (no deps), time_h (h), ab (time_h), edge (ab+d2),
    // time_v (independent), node (edge).
    k_d2<<<(E_ + 255) / 256, 256>>>(x, ei);
    k_time_h<<<1250, 256, smem_h>>>(h, whr, whi);
    k_ab<<<1250, 256, smem_ab>>>(We1, be1);
    k_edge<<<5000, 256, smem_edge>>>(ei, We1, We2, be2, Wg, bg);
    k_time_v<<<(BN_ * 3 + 255) / 256, 256>>>(vel, wvr, wvi, out + HTOT_);
    k_node<<<1250, 256, smem_node>>>(Wn1, bn1, Wn2, bn2, out);
}

// round 7
// speedup vs baseline: 2.0387x; 1.0030x over previous
#include <cuda_runtime.h>

// Problem constants
#define BN_   10000
#define T_    8
#define C_    64
#define NM_   3
#define E_    160000
#define NTOT_ (T_ * BN_)        // 80000 node-rows
#define HTOT_ (NTOT_ * C_)      // 5,120,000

// Scratch (device globals: allocation-free rule)
__device__ __align__(16) float g_hnew[HTOT_];
__device__ __align__(16) float g_A[HTOT_];
__device__ __align__(16) float g_B[HTOT_];
__device__ __align__(16) float g_agg[HTOT_];
__device__ __align__(16) float g_d2[E_];

__constant__ float CT8[8] = {1.f,  0.70710678118654752f, 0.f, -0.70710678118654752f,
                             -1.f, -0.70710678118654752f, 0.f,  0.70710678118654752f};
__constant__ float ST8[8] = {0.f,  0.70710678118654752f, 1.f,  0.70710678118654752f,
                             0.f, -0.70710678118654752f, -1.f, -0.70710678118654752f};

typedef unsigned long long ull;

__device__ __forceinline__ float silu_f(float x)    { return x / (1.f + __expf(-x)); }
__device__ __forceinline__ float sigmoid_f(float x) { return 1.f / (1.f + __expf(-x)); }

__device__ __forceinline__ ull pk2(float lo, float hi) {
    ull r; asm("mov.b64 %0,{%1,%2};" : "=l"(r) : "f"(lo), "f"(hi)); return r;
}
__device__ __forceinline__ void upk2(ull v, float& lo, float& hi) {
    asm("mov.b64 {%0,%1},%2;" : "=f"(lo), "=f"(hi) : "l"(v));
}
__device__ __forceinline__ ull f2fma(ull a, ull b, ull c) {
    ull d; asm("fma.rn.f32x2 %0,%1,%2,%3;" : "=l"(d) : "l"(a), "l"(b), "l"(c)); return d;
}

// ---------------------------------------------------------------------------
// Kernel 1: TimeConv on h.  8 nodes/block, 2 nodes per phase-B thread.
// ---------------------------------------------------------------------------
__global__ void __launch_bounds__(256, 2) k_time_h(const float* __restrict__ h,
                                                   const float* __restrict__ whr,
                                                   const float* __restrict__ whi) {
    extern __shared__ float sm[];
    float* sWr12 = sm;            // [i*64+o]*2 : (wr1, wr2)
    float* sWi12 = sm + 8192;     // (wi1, wi2)
    float* sWr0  = sm + 16384;    // wr0
    float* sxf   = sm + 20480;    // [8 slot][64 i][8]
    const int tid = threadIdx.x;

    for (int idx = tid; idx < 4096; idx += 256) {
        int base = idx * 3;                  // (i*64+o)*3
        sWr12[idx * 2]     = whr[base + 1];
        sWr12[idx * 2 + 1] = whr[base + 2];
        sWi12[idx * 2]     = whi[base + 1];
        sWi12[idx * 2 + 1] = whi[base + 2];
        sWr0[idx]          = whr[base];
    }

    const int grp = tid >> 6;
    const int l   = tid & 63;
    const int node0 = blockIdx.x * 8 + grp * 2;

    // Phase A: rfft per (node, channel=l)
#pragma unroll
    for (int pp = 0; pp < 2; ++pp) {
        int node = node0 + pp;
        float xv[8];
#pragma unroll
        for (int t = 0; t < 8; ++t) xv[t] = h[t * (BN_ * C_) + node * C_ + l];
        float xr0 = 0.f, xr1 = 0.f, xi1 = 0.f, xr2 = 0.f, xi2 = 0.f;
#pragma unroll
        for (int t = 0; t < 8; ++t) {
            xr0 += xv[t];
            xr1 += xv[t] * CT8[t];
            xi1 -= xv[t] * ST8[t];
            xr2 += xv[t] * CT8[(2 * t) & 7];
            xi2 -= xv[t] * ST8[(2 * t) & 7];
        }
        float* p = sxf + (grp * 2 + pp) * 512 + l * 8;
        p[0] = xr1;  p[1] = xr2;
        p[2] = xi1;  p[3] = xi2;
        p[4] = -xi1; p[5] = -xi2;
        p[6] = xr0;  p[7] = 0.f;
    }
    __syncthreads();

    // Phase B: complex mix for o = l, 2 nodes
    ull omrA = pk2(0.f, 0.f), omiA = omrA, omrB = omrA, omiB = omrA;
    float om0A = 0.f, om0B = 0.f;
    const float* xA = sxf + grp * 1024;
    const float* xB = xA + 512;
#pragma unroll 4
    for (int i = 0; i < 64; ++i) {
        ull wr12 = *(const ull*)(sWr12 + (i * 64 + l) * 2);
        ull wi12 = *(const ull*)(sWi12 + (i * 64 + l) * 2);
        float wr0 = sWr0[i * 64 + l];
        const float* pa = xA + i * 8;
        const float* pb = xB + i * 8;
        ull xra = *(const ull*)pa;
        ull xia = *(const ull*)(pa + 2);
        ull nxa = *(const ull*)(pa + 4);
        ull xrb = *(const ull*)pb;
        ull xib = *(const ull*)(pb + 2);
        ull nxb = *(const ull*)(pb + 4);
        omrA = f2fma(xra, wr12, omrA); omrA = f2fma(nxa, wi12, omrA);
        omiA = f2fma(xra, wi12, omiA); omiA = f2fma(xia, wr12, omiA);
        om0A = fmaf(pa[6], wr0, om0A);
        omrB = f2fma(xrb, wr12, omrB); omrB = f2fma(nxb, wi12, omrB);
        omiB = f2fma(xrb, wi12, omiB); omiB = f2fma(xib, wr12, omiB);
        om0B = fmaf(pb[6], wr0, om0B);
    }

    // Phase C: irfft + leaky residual
#pragma unroll
    for (int pp = 0; pp < 2; ++pp) {
        int node = node0 + pp;
        float or1, or2, oi1, oi2, o0;
        if (pp == 0) { upk2(omrA, or1, or2); upk2(omiA, oi1, oi2); o0 = om0A; }
        else         { upk2(omrB, or1, or2); upk2(omiB, oi1, oi2); o0 = om0B; }
#pragma unroll
        for (int t = 0; t < 8; ++t) {
            float val = o0
                + 2.f * (or1 * CT8[t]           - oi1 * ST8[t])
                + 2.f * (or2 * CT8[(2 * t) & 7] - oi2 * ST8[(2 * t) & 7]);
            val *= 0.125f;
            float lr = val > 0.f ? val : 0.2f * val;
            int off = t * (BN_ * C_) + node * C_ + l;
            g_hnew[off] = h[off] + lr;
        }
    }
}

// ---------------------------------------------------------------------------
// Kernel 2: TimeConvX on velocity
// ---------------------------------------------------------------------------
__global__ void k_time_v(const float* __restrict__ vel,
                         const float* __restrict__ wvr,
                         const float* __restrict__ wvi,
                         float* __restrict__ out) {
    int j = blockIdx.x * blockDim.x + threadIdx.x;
    if (j >= BN_ * 3) return;
    int b = j / 3, d = j - b * 3;
    float xv[8];
#pragma unroll
    for (int t = 0; t < 8; ++t) xv[t] = vel[b * (T_ * 3) + t * 3 + d];
    float xr0 = 0.f, xr1 = 0.f, xi1 = 0.f, xr2 = 0.f, xi2 = 0.f;
#pragma unroll
    for (int t = 0; t < 8; ++t) {
        xr0 += xv[t];
        xr1 += xv[t] * CT8[t];
        xi1 -= xv[t] * ST8[t];
        xr2 += xv[t] * CT8[(2 * t) & 7];
        xi2 -= xv[t] * ST8[(2 * t) & 7];
    }
    float w0r = wvr[0];
    float w1r = wvr[1], w1i = wvi[1];
    float w2r = wvr[2], w2i = wvi[2];
    float yr0 = xr0 * w0r;
    float yr1 = xr1 * w1r - xi1 * w1i;
    float yi1 = xr1 * w1i + xi1 * w1r;
    float yr2 = xr2 * w2r - xi2 * w2i;
    float yi2 = xr2 * w2i + xi2 * w2r;
#pragma unroll
    for (int t = 0; t < 8; ++t) {
        float val = 0.125f * (yr0
            + 2.f * (yr1 * CT8[t]           - yi1 * ST8[t])
            + 2.f * (yr2 * CT8[(2 * t) & 7] - yi2 * ST8[(2 * t) & 7]));
        out[b * (T_ * 3) + t * 3 + d] = xv[t] + val;
    }
}

// ---------------------------------------------------------------------------
// Kernel 3: per-base-edge squared distance
// ---------------------------------------------------------------------------
__global__ void k_d2(const float* __restrict__ x, const int* __restrict__ ei) {
    int e = blockIdx.x * blockDim.x + threadIdx.x;
    if (e >= E_) return;
    int r = ei[e];
    int c = ei[E_ + e];
    float dx = x[r * 3 + 0] - x[c * 3 + 0];
    float dy = x[r * 3 + 1] - x[c * 3 + 1];
    float dz = x[r * 3 + 2] - x[c * 3 + 2];
    g_d2[e] = dx * dx + dy * dy + dz * dz;
}

// ---------------------------------------------------------------------------
// Kernel 4: A/B precompute as register-tiled GEMM.
// M=64 nodes/block, N=128 (A|B), K=64. 256 thr, thread tile 4m x 8n.
// ---------------------------------------------------------------------------
__global__ void __launch_bounds__(256, 4) k_ab(const float* __restrict__ We1,
                                               const float* __restrict__ be1) {
    extern __shared__ float sm[];
    float* sX = sm;              // [64][68]
    float* sW = sm + 4352;       // [64][132]
    float* sbias = sm + 12800;   // [128]
    const int tid = threadIdx.x;

    for (int idx = tid; idx < 8192; idx += 256) {
        int k = idx >> 7, n = idx & 127;
        float v = (n < 64) ? We1[k * 64 + n] : We1[(64 + k) * 64 + (n - 64)];
        sW[k * 132 + n] = v;
    }
    if (tid < 128) sbias[tid] = (tid < 64) ? be1[tid] : 0.f;

    const int nb = blockIdx.x * 64;
    {
        int row = tid >> 2, l4 = tid & 3;
        const float4* hp = (const float4*)(g_hnew + (size_t)(nb + row) * 64 + l4 * 16);
        float4* agp = (float4*)(g_agg + (size_t)(nb + row) * 64 + l4 * 16);
        float4* sx4 = (float4*)(sX + row * 68 + l4 * 16);
        float4 z = make_float4(0.f, 0.f, 0.f, 0.f);
#pragma unroll
        for (int jj = 0; jj < 4; ++jj) { sx4[jj] = hp[jj]; agp[jj] = z; }
    }
    __syncthreads();

    const int lane = tid & 31, w = tid >> 5;
    const int mw = w & 1, nw = w >> 1;         // nw 0..3
    const int mq = lane >> 2, nq = lane & 3;
    const int m0 = mw * 32 + mq;               // + i*8
    const int nbase = nw * 32 + nq * 4;        // + 16j

    ull acc[16];
#pragma unroll
    for (int i = 0; i < 4; ++i)
#pragma unroll
        for (int jj = 0; jj < 2; ++jj) {
            int n0 = nbase + 16 * jj;
            acc[i * 4 + jj * 2]     = pk2(sbias[n0],     sbias[n0 + 1]);
            acc[i * 4 + jj * 2 + 1] = pk2(sbias[n0 + 2], sbias[n0 + 3]);
        }

    const float* xp = sX + m0 * 68;
#pragma unroll 2
    for (int k4 = 0; k4 < 16; ++k4) {
        float xa[4][4];
#pragma unroll
        for (int i = 0; i < 4; ++i) {
            float4 v = *(const float4*)(xp + i * 8 * 68 + k4 * 4);
            xa[i][0] = v.x; xa[i][1] = v.y; xa[i][2] = v.z; xa[i][3] = v.w;
        }
#pragma unroll
        for (int kk = 0; kk < 4; ++kk) {
            const float* wrow = sW + (k4 * 4 + kk) * 132 + nbase;
            ull wv[4];
            wv[0] = *(const ull*)(wrow);
            wv[1] = *(const ull*)(wrow + 2);
            wv[2] = *(const ull*)(wrow + 16);
            wv[3] = *(const ull*)(wrow + 18);
#pragma unroll
            for (int i = 0; i < 4; ++i) {
                ull mk = pk2(xa[i][kk], xa[i][kk]);
#pragma unroll
                for (int jj = 0; jj < 4; ++jj)
                    acc[i * 4 + jj] = f2fma(mk, wv[jj], acc[i * 4 + jj]);
            }
        }
    }

#pragma unroll
    for (int i = 0; i < 4; ++i) {
        int node = nb + m0 + i * 8;
#pragma unroll
        for (int jj = 0; jj < 2; ++jj) {
            int n0 = nbase + 16 * jj;
            float4 v;
            upk2(acc[i * 4 + jj * 2],     v.x, v.y);
            upk2(acc[i * 4 + jj * 2 + 1], v.z, v.w);
            if (n0 < 64) *(float4*)(g_A + (size_t)node * 64 + n0) = v;
            else         *(float4*)(g_B + (size_t)node * 64 + (n0 - 64)) = v;
        }
    }
}

// ---------------------------------------------------------------------------
// Kernel 5: edge messages. 256 edges/block. 2 blocks/SM for phase overlap.
// ---------------------------------------------------------------------------
__global__ void __launch_bounds__(256, 2) k_edge(const int* __restrict__ ei,
                                                 const float* __restrict__ We1,
                                                 const float* __restrict__ We2,
                                                 const float* __restrict__ be2,
                                                 const float* __restrict__ Wg,
                                                 const float* __restrict__ bg) {
    extern __shared__ float sm[];
    float* sm1 = sm;                    // [256][68]
    float* sW2 = sm + 17408;            // [64][68]
    float* swl = sm + 21760;            // [64]
    float* sg  = sm + 21824;            // [64]
    float* sb2 = sm + 21888;            // [64]
    int*   srb = (int*)(sm + 21952);    // [256]
    const int tid = threadIdx.x;

    for (int idx = tid; idx < 4096; idx += 256)
        sW2[(idx >> 6) * 68 + (idx & 63)] = We2[idx];
    if (tid < 64) {
        swl[tid] = We1[128 * 64 + tid];
        sg[tid]  = Wg[tid];
        sb2[tid] = be2[tid];
    }
    __syncthreads();

    const int t  = blockIdx.x / 625;
    const int jb = (blockIdx.x - t * 625) * 256;

    // Phase 1
    {
        const int eIdx = tid >> 2, l4 = tid & 3;
#pragma unroll
        for (int p = 0; p < 4; ++p) {
            int e = p * 64 + eIdx;
            int j = jb + e;
            int rb = t * BN_ + __ldg(ei + j);
            int cb = t * BN_ + __ldg(ei + E_ + j);
            if (l4 == 0) srb[e] = rb;
            float dd = g_d2[j];
            const float4* Ap = (const float4*)(g_A + (size_t)rb * 64 + l4 * 16);
            const float4* Bp = (const float4*)(g_B + (size_t)cb * 64 + l4 * 16);
            const float4* wl = (const float4*)(swl + l4 * 16);
            float4* dst = (float4*)(sm1 + e * 68 + l4 * 16);
#pragma unroll
            for (int jj = 0; jj < 4; ++jj) {
                float4 a = Ap[jj], b = Bp[jj], ww = wl[jj];
                float4 o;
                o.x = silu_f(a.x + b.x + dd * ww.x);
                o.y = silu_f(a.y + b.y + dd * ww.y);
                o.z = silu_f(a.z + b.z + dd * ww.z);
                o.w = silu_f(a.w + b.w + dd * ww.w);
                dst[jj] = o;
            }
        }
    }
    __syncthreads();

    // Phase 2: GEMM  (warp w: edges w*32..w*32+31, all 64 outputs)
    const int lane = tid & 31, w = tid >> 5;
    const int mq = lane >> 2, nq = lane & 3;
    const int m0 = w * 32 + mq;                 // + i*8
    const int nbq = nq * 4;                     // + 16j

    ull acc[32];
#pragma unroll
    for (int i = 0; i < 4; ++i)
#pragma unroll
        for (int j = 0; j < 4; ++j) {
            int n0 = nbq + 16 * j;
            acc[i * 8 + j * 2]     = pk2(sb2[n0],     sb2[n0 + 1]);
            acc[i * 8 + j * 2 + 1] = pk2(sb2[n0 + 2], sb2[n0 + 3]);
        }

    const float* xp = sm1 + m0 * 68;
#pragma unroll 1
    for (int k4 = 0; k4 < 16; ++k4) {
        float xa[4][4];
#pragma unroll
        for (int i = 0; i < 4; ++i) {
            float4 v = *(const float4*)(xp + i * 8 * 68 + k4 * 4);
            xa[i][0] = v.x; xa[i][1] = v.y; xa[i][2] = v.z; xa[i][3] = v.w;
        }
#pragma unroll
        for (int kk = 0; kk < 4; ++kk) {
            const float* wrow = sW2 + (k4 * 4 + kk) * 68 + nbq;
            ull wv[8];
#pragma unroll
            for (int j = 0; j < 4; ++j) {
                wv[2 * j]     = *(const ull*)(wrow + 16 * j);
                wv[2 * j + 1] = *(const ull*)(wrow + 16 * j + 2);
            }
#pragma unroll
            for (int i = 0; i < 4; ++i) {
                ull mk = pk2(xa[i][kk], xa[i][kk]);
#pragma unroll
                for (int jj = 0; jj < 8; ++jj)
                    acc[i * 8 + jj] = f2fma(mk, wv[jj], acc[i * 8 + jj]);
            }
        }
    }

    // Phase 3
    const float bgv = __ldg(bg);
#pragma unroll
    for (int i = 0; i < 4; ++i) {
        int m = m0 + i * 8;
        float v[16];
        float gp = 0.f;
#pragma unroll
        for (int j = 0; j < 4; ++j) {
            int n0 = nbq + 16 * j;
            float a, b, c, d;
            upk2(acc[i * 8 + j * 2],     a, b);
            upk2(acc[i * 8 + j * 2 + 1], c, d);
            a = silu_f(a); b = silu_f(b); c = silu_f(c); d = silu_f(d);
            v[j * 4] = a; v[j * 4 + 1] = b; v[j * 4 + 2] = c; v[j * 4 + 3] = d;
            gp += a * sg[n0] + b * sg[n0 + 1] + c * sg[n0 + 2] + d * sg[n0 + 3];
        }
        gp += __shfl_xor_sync(0xffffffffu, gp, 1);
        gp += __shfl_xor_sync(0xffffffffu, gp, 2);
        float gate = sigmoid_f(gp + bgv);
        float* ag = g_agg + (size_t)srb[m] * 64 + nbq;
#pragma unroll
        for (int j = 0; j < 4; ++j) {
            asm volatile("red.global.add.v4.f32 [%0], {%1,%2,%3,%4};" ::
                "l"(ag + 16 * j),
                "f"(gate * v[j * 4]),     "f"(gate * v[j * 4 + 1]),
                "f"(gate * v[j * 4 + 2]), "f"(gate * v[j * 4 + 3]) : "memory");
        }
    }
}

// ---------------------------------------------------------------------------
// Kernel 6: node update as two register-tiled GEMMs.
// ---------------------------------------------------------------------------
__global__ void __launch_bounds__(256, 2) k_node(const float* __restrict__ Wn1,
                                                 const float* __restrict__ bn1,
                                                 const float* __restrict__ Wn2,
                                                 const float* __restrict__ bn2,
                                                 float* __restrict__ out) {
    extern __shared__ float sm[];
    float* sX  = sm;            // [64][132] = [h | agg]
    float* sW1 = sm + 8448;     // [128][68]
    float* sU  = sm + 17152;    // [64][68]
    float* sW2 = sm + 21504;    // [64][68]
    float* sb1 = sm + 25856;    // [64]
    float* sb2 = sm + 25920;    // [64]
    const int tid = threadIdx.x;

    for (int idx = tid; idx < 8192; idx += 256)
        sW1[(idx >> 6) * 68 + (idx & 63)] = Wn1[idx];
    for (int idx = tid; idx < 4096; idx += 256)
        sW2[(idx >> 6) * 68 + (idx & 63)] = Wn2[idx];
    if (tid < 64) { sb1[tid] = bn1[tid]; sb2[tid] = bn2[tid]; }

    const int nb = blockIdx.x * 64;
    {
        int row = tid >> 2, l4 = tid & 3;
        const float4* hp = (const float4*)(g_hnew + (size_t)(nb + row) * 64 + l4 * 16);
        const float4* gp = (const float4*)(g_agg  + (size_t)(nb + row) * 64 + l4 * 16);
        float4* sxh = (float4*)(sX + row * 132 + l4 * 16);
        float4* sxa = (float4*)(sX + row * 132 + 64 + l4 * 16);
#pragma unroll
        for (int jj = 0; jj < 4; ++jj) { sxh[jj] = hp[jj]; sxa[jj] = gp[jj]; }
    }
    __syncthreads();

    const int lane = tid & 31, w = tid >> 5;
    const int mw = w & 3, nw = w >> 2;          // nw 0..1
    const int mq = lane >> 2, nq = lane & 3;
    const int m0 = mw * 16 + mq;                // + i*8, i 0..1
    const int nbase = nw * 32 + nq * 4;         // + 16j, j 0..1

    // ---- layer 1 (K = 128) ----
    ull acc[8];
#pragma unroll
    for (int i = 0; i < 2; ++i)
#pragma unroll
        for (int jj = 0; jj < 2; ++jj) {
            int n0 = nbase + 16 * jj;
            acc[i * 4 + jj * 2]     = pk2(sb1[n0],     sb1[n0 + 1]);
            acc[i * 4 + jj * 2 + 1] = pk2(sb1[n0 + 2], sb1[n0 + 3]);
        }
    const float* xp = sX + m0 * 132;
#pragma unroll 2
    for (int k4 = 0; k4 < 32; ++k4) {
        float xa[2][4];
#pragma unroll
        for (int i = 0; i < 2; ++i) {
            float4 v = *(const float4*)(xp + i * 8 * 132 + k4 * 4);
            xa[i][0] = v.x; xa[i][1] = v.y; xa[i][2] = v.z; xa[i][3] = v.w;
        }
#pragma unroll
        for (int kk = 0; kk < 4; ++kk) {
            const float* wrow = sW1 + (k4 * 4 + kk) * 68 + nbase;
            ull wv[4];
            wv[0] = *(const ull*)(wrow);
            wv[1] = *(const ull*)(wrow + 2);
            wv[2] = *(const ull*)(wrow + 16);
            wv[3] = *(const ull*)(wrow + 18);
#pragma unroll
            for (int i = 0; i < 2; ++i) {
                ull mk = pk2(xa[i][kk], xa[i][kk]);
#pragma unroll
                for (int jj = 0; jj < 4; ++jj)
                    acc[i * 4 + jj] = f2fma(mk, wv[jj], acc[i * 4 + jj]);
            }
        }
    }
#pragma unroll
    for (int i = 0; i < 2; ++i) {
        int m = m0 + i * 8;
#pragma unroll
        for (int jj = 0; jj < 2; ++jj) {
            int n0 = nbase + 16 * jj;
            float4 v;
            upk2(acc[i * 4 + jj * 2],     v.x, v.y);
            upk2(acc[i * 4 + jj * 2 + 1], v.z, v.w);
            v.x = silu_f(v.x); v.y = silu_f(v.y);
            v.z = silu_f(v.z); v.w = silu_f(v.w);
            *(float4*)(sU + m * 68 + n0) = v;
        }
    }
    __syncthreads();

    // ---- layer 2 (K = 64) ----
    ull acc2[8];
#pragma unroll
    for (int i = 0; i < 2; ++i)
#pragma unroll
        for (int jj = 0; jj < 2; ++jj) {
            int n0 = nbase + 16 * jj;
            acc2[i * 4 + jj * 2]     = pk2(sb2[n0],     sb2[n0 + 1]);
            acc2[i * 4 + jj * 2 + 1] = pk2(sb2[n0 + 2], sb2[n0 + 3]);
        }
    const float* up = sU + m0 * 68;
#pragma unroll 2
    for (int k4 = 0; k4 < 16; ++k4) {
        float xa[2][4];
#pragma unroll
        for (int i = 0; i < 2; ++i) {
            float4 v = *(const float4*)(up + i * 8 * 68 + k4 * 4);
            xa[i][0] = v.x; xa[i][1] = v.y; xa[i][2] = v.z; xa[i][3] = v.w;
        }
#pragma unroll
        for (int kk = 0; kk < 4; ++kk) {
            const float* wrow = sW2 + (k4 * 4 + kk) * 68 + nbase;
            ull wv[4];
            wv[0] = *(const ull*)(wrow);
            wv[1] = *(const ull*)(wrow + 2);
            wv[2] = *(const ull*)(wrow + 16);
            wv[3] = *(const ull*)(wrow + 18);
#pragma unroll
            for (int i = 0; i < 2; ++i) {
                ull mk = pk2(xa[i][kk], xa[i][kk]);
#pragma unroll
                for (int jj = 0; jj < 4; ++jj)
                    acc2[i * 4 + jj] = f2fma(mk, wv[jj], acc2[i * 4 + jj]);
            }
        }
    }
    // residual + store
#pragma unroll
    for (int i = 0; i < 2; ++i) {
        int m = m0 + i * 8;
        int node = nb + m;
#pragma unroll
        for (int jj = 0; jj < 2; ++jj) {
            int n0 = nbase + 16 * jj;
            float4 v;
            upk2(acc2[i * 4 + jj * 2],     v.x, v.y);
            upk2(acc2[i * 4 + jj * 2 + 1], v.z, v.w);
            float4 hv = *(const float4*)(sX + m * 132 + n0);
            v.x += hv.x; v.y += hv.y; v.z += hv.z; v.w += hv.w;
            *(float4*)(out + (size_t)node * 64 + n0) = v;
        }
    }
}

// ---------------------------------------------------------------------------
extern "C" void kernel_launch(void* const* d_in, const int* in_sizes, int n_in,
                              void* d_out, int out_size) {
    const float* h   = (const float*)d_in[0];
    const float* x   = (const float*)d_in[1];
    const float* vel = (const float*)d_in[2];
    const int*   ei  = (const int*)d_in[3];
    const float* whr = (const float*)d_in[4];
    const float* whi = (const float*)d_in[5];
    const float* wvr = (const float*)d_in[6];
    const float* wvi = (const float*)d_in[7];
    const float* We1 = (const float*)d_in[8];
    const float* be1 = (const float*)d_in[9];
    const float* We2 = (const float*)d_in[10];
    const float* be2 = (const float*)d_in[11];
    const float* Wg  = (const float*)d_in[12];
    const float* bg  = (const float*)d_in[13];
    const float* Wn1 = (const float*)d_in[14];
    const float* bn1 = (const float*)d_in[15];
    const float* Wn2 = (const float*)d_in[16];
    const float* bn2 = (const float*)d_in[17];
    float* out = (float*)d_out;

    (void)in_sizes; (void)n_in; (void)out_size;

    const int smem_h    = 24576 * 4;  // 98304
    const int smem_ab   = 12928 * 4;  // 51712
    const int smem_edge = 22208 * 4;  // 88832
    const int smem_node = 25984 * 4;  // 103936
    cudaFuncSetAttribute(k_time_h, cudaFuncAttributeMaxDynamicSharedMemorySize, smem_h);
    cudaFuncSetAttribute(k_ab,     cudaFuncAttributeMaxDynamicSharedMemorySize, smem_ab);
    cudaFuncSetAttribute(k_edge,   cudaFuncAttributeMaxDynamicSharedMemorySize, smem_edge);
    cudaFuncSetAttribute(k_node,   cudaFuncAttributeMaxDynamicSharedMemorySize, smem_node);

    // Launch order chosen so k_edge is the 4th launch (ncu capture slot),
    // dependency-safe: d2 (no deps), time_h (h), ab (time_h), edge (ab+d2),
    // time_v (independent), node (edge).
    k_d2<<<(E_ + 255) / 256, 256>>>(x, ei);
    k_time_h<<<1250, 256, smem_h>>>(h, whr, whi);
    k_ab<<<1250, 256, smem_ab>>>(We1, be1);
    k_edge<<<5000, 256, smem_edge>>>(ei, We1, We2, be2, Wg, bg);
    k_time_v<<<(BN_ * 3 + 255) / 256, 256>>>(vel, wvr, wvi, out + HTOT_);
    k_node<<<1250, 256, smem_node>>>(Wn1, bn1, Wn2, bn2, out);
}